// round 8
// baseline (speedup 1.0000x reference)
#include <cuda_runtime.h>
#include <cuda_bf16.h>
#include <cstdint>
#include <math.h>

#define HID  2048
#define SEQ  2048
#define BATCH 4
#define NQKV 6144   // 3*HID

#define STAGES 3
#define BK 64
#define SSTRIDE 9216          // bf16 elems per operand per stage (128*72)
#define SMEM_BYTES (2 * STAGES * SSTRIDE * 2)   // 110592

// ---------------- scratch (device globals; no allocations allowed) ----------
__device__ __align__(16) __nv_bfloat16 g_xn  [BATCH * SEQ * HID];    // 32 MB
__device__ __align__(16) __nv_bfloat16 g_wqkv[HID * NQKV];           // 24 MB
__device__ __align__(16) __nv_bfloat16 g_wo  [HID * HID];            //  8 MB
__device__ __align__(16) __nv_bfloat16 g_qkv [BATCH * SEQ * NQKV];   // 96 MB
__device__ __align__(16) float         g_sc  [BATCH * SEQ * SEQ];    // 64 MB
__device__ __align__(16) __nv_bfloat16 g_pr  [BATCH * SEQ * SEQ];    // 32 MB
__device__ __align__(16) __nv_bfloat16 g_av  [BATCH * SEQ * HID];    // 32 MB

// ---------------- helpers ----------------------------------------------------
__device__ __forceinline__ void cpa16(uint32_t dst, const void* src) {
    asm volatile("cp.async.cg.shared.global [%0], [%1], 16;" :: "r"(dst), "l"(src));
}
__device__ __forceinline__ void cpa_commit() {
    asm volatile("cp.async.commit_group;");
}
template <int N>
__device__ __forceinline__ void cpa_wait() {
    asm volatile("cp.async.wait_group %0;" :: "n"(N));
}

// ---------------- fp32 -> bf16 convert ---------------------------------------
__global__ void cvt_kernel(const float4* __restrict__ in, uint32_t* __restrict__ out, int n4) {
    int i = blockIdx.x * blockDim.x + threadIdx.x;
    if (i < n4) {
        float4 v = in[i];
        __nv_bfloat162 a = __float22bfloat162_rn(make_float2(v.x, v.y));
        __nv_bfloat162 b = __float22bfloat162_rn(make_float2(v.z, v.w));
        out[i * 2 + 0] = *reinterpret_cast<uint32_t*>(&a);
        out[i * 2 + 1] = *reinterpret_cast<uint32_t*>(&b);
    }
}

// ---------------- LayerNorm: one block per row, bf16 out ---------------------
__global__ void ln_kernel(const float* __restrict__ x,
                          const float* __restrict__ gamma,
                          const float* __restrict__ beta,
                          __nv_bfloat16* __restrict__ out) {
    const int row = blockIdx.x;
    const float* xr = x + (size_t)row * HID;
    __nv_bfloat16* orow = out + (size_t)row * HID;
    const int tid = threadIdx.x;

    float v[8];
    float s = 0.f, s2 = 0.f;
#pragma unroll
    for (int i = 0; i < 8; i++) {
        float val = xr[tid + i * 256];
        v[i] = val; s += val; s2 += val * val;
    }
    __shared__ float red[2][8];
#pragma unroll
    for (int o = 16; o > 0; o >>= 1) {
        s  += __shfl_down_sync(0xffffffffu, s,  o);
        s2 += __shfl_down_sync(0xffffffffu, s2, o);
    }
    const int w = tid >> 5, l = tid & 31;
    if (l == 0) { red[0][w] = s; red[1][w] = s2; }
    __syncthreads();
    if (w == 0) {
        float a  = red[0][l & 7];
        float b2 = red[1][l & 7];
#pragma unroll
        for (int o = 4; o > 0; o >>= 1) {
            a  += __shfl_down_sync(0xffffffffu, a,  o);
            b2 += __shfl_down_sync(0xffffffffu, b2, o);
        }
        if (l == 0) { red[0][0] = a; red[1][0] = b2; }
    }
    __syncthreads();
    const float mean = red[0][0] * (1.f / HID);
    const float var  = red[1][0] * (1.f / HID) - mean * mean;
    const float rstd = rsqrtf(var + 1e-5f);
#pragma unroll
    for (int i = 0; i < 8; i++) {
        int h = tid + i * 256;
        orow[h] = __float2bfloat16((v[i] - mean) * rstd * gamma[h] + beta[h]);
    }
}

// ---------------- causal softmax: fp32 scores in, bf16 probs out -------------
// Zeroes only up to the 128-aligned end of the diagonal block (PV clips there).
__global__ void softmax_kernel(float* __restrict__ sc,
                               __nv_bfloat16* __restrict__ pr, float scale) {
    const int row = blockIdx.x;            // b*SEQ + q
    const int q = row & (SEQ - 1);
    float* p = sc + (size_t)row * SEQ;
    __nv_bfloat16* po = pr + (size_t)row * SEQ;
    const int n = q + 1;
    const int nend = ((q >> 7) + 1) << 7;  // PV reads only [0, nend)
    const int tid = threadIdx.x;
    __shared__ float red[8];

    float mx = -1e30f;
    for (int t = tid; t < n; t += 256) mx = fmaxf(mx, p[t] * scale);
#pragma unroll
    for (int o = 16; o > 0; o >>= 1) mx = fmaxf(mx, __shfl_down_sync(0xffffffffu, mx, o));
    if ((tid & 31) == 0) red[tid >> 5] = mx;
    __syncthreads();
    if (tid < 32) {
        float a = red[tid & 7];
#pragma unroll
        for (int o = 4; o > 0; o >>= 1) a = fmaxf(a, __shfl_down_sync(0xffffffffu, a, o));
        if (tid == 0) red[0] = a;
    }
    __syncthreads();
    mx = red[0];
    __syncthreads();

    float sum = 0.f;
    for (int t = tid; t < n; t += 256) {
        float e = __expf(p[t] * scale - mx);
        p[t] = e;
        sum += e;
    }
#pragma unroll
    for (int o = 16; o > 0; o >>= 1) sum += __shfl_down_sync(0xffffffffu, sum, o);
    if ((tid & 31) == 0) red[tid >> 5] = sum;
    __syncthreads();
    if (tid < 32) {
        float a = red[tid & 7];
#pragma unroll
        for (int o = 4; o > 0; o >>= 1) a += __shfl_down_sync(0xffffffffu, a, o);
        if (tid == 0) red[0] = a;
    }
    __syncthreads();
    const float inv = 1.f / red[0];
    for (int t = tid; t < n; t += 256) po[t] = __float2bfloat16(p[t] * inv);
    for (int t = n + tid; t < nend; t += 256) po[t] = __float2bfloat16(0.f);
}

// ---------------- bf16 tensor-core GEMM (3-stage, BK=64, frag dbl-buffer) ----
// C[M,N] = A[M,K] @ B. A row-major bf16 (lda).
// BKMAJ=true:  B stored [N,K] k-contig (ldb) -> A @ B^T.
// BKMAJ=false: B stored [K,N] n-contig (ldb).
// EPI: 0 = fp32 out, 1 = fp32 out + residual R, 2 = bf16 out.
// Block 128x128x64, 8 warps of 64x32, m16n8k16 bf16 mma, 2 CTAs/SM.
// Register-level fragment double-buffer: LDSM for kc+1 overlaps HMMAs of kc.
template <bool BKMAJ, int EPI, bool CSKIP, bool CKLIM>
__global__ void __launch_bounds__(256, 2)
gemm_bf16(const __nv_bfloat16* __restrict__ A, int lda, long sA,
          const __nv_bfloat16* __restrict__ B, int ldb, long sB,
          void* __restrict__ Cv, int ldc, long sC,
          int Kdim,
          const float* __restrict__ R, int ldr) {
    const int mb = blockIdx.y, nb = blockIdx.x;
    if (CSKIP && nb > mb) return;   // fully-masked upper-triangular score block

    A += (long)blockIdx.z * sA;
    B += (long)blockIdx.z * sB;

    const int kend = CKLIM ? min(Kdim, (mb + 1) * 128) : Kdim;
    const int nK = kend >> 6;   // BK = 64; >= 2 for all our shapes

    extern __shared__ __align__(16) __nv_bfloat16 sm[];
    // A stages: sm[st*SSTRIDE], layout [128 rows][72]   (64 k + pad 8)
    // B stages: sm[STAGES*SSTRIDE + st*SSTRIDE],
    //           BKMAJ ? [128 n][72 k] : [64 k][136 n]
    const uint32_t smBase = (uint32_t)__cvta_generic_to_shared(sm);
    const uint32_t aBase = smBase;
    const uint32_t bBase = smBase + STAGES * SSTRIDE * 2;

    const int tid = threadIdx.x;
    const int warp = tid >> 5, lane = tid & 31;
    const int gid = lane >> 2, tig = lane & 3;
    const int wm = (warp & 1) * 64, wn = (warp >> 1) * 32;
    const int bm0 = mb * 128, bn0 = nb * 128;

    float c[4][4][4];
#pragma unroll
    for (int i = 0; i < 4; i++)
#pragma unroll
        for (int j = 0; j < 4; j++)
#pragma unroll
            for (int k = 0; k < 4; k++) c[i][j][k] = 0.f;

    // ldmatrix per-lane coordinates
    const int arow = (lane & 7) + ((lane >> 3) & 1) * 8;
    const int acol = ((lane >> 4) & 1) * 8;
    const int ln8 = lane & 7, sel = lane >> 3;
    const int bt_row = ((sel >> 1) & 1) * 8 + ln8;   // BKMAJ=true: n within 16
    const int bt_col = (sel & 1) * 8;                // k-half
    const int bf_row = (sel & 1) * 8 + ln8;          // BKMAJ=false: k within 16
    const int bf_col = ((sel >> 1) & 1) * 8;         // n within 16

    auto fillA = [&](int st, int k0) {
#pragma unroll
        for (int p = 0; p < 4; p++) {
            int fid = tid + p * 256;
            int r = fid >> 3, kq = fid & 7;
            cpa16(aBase + (st * SSTRIDE + r * 72 + kq * 8) * 2,
                  A + (size_t)(bm0 + r) * lda + k0 + kq * 8);
        }
    };
    auto fillB = [&](int st, int k0) {
#pragma unroll
        for (int p = 0; p < 4; p++) {
            int fid = tid + p * 256;
            if (BKMAJ) {
                int r = fid >> 3, kq = fid & 7;
                cpa16(bBase + (st * SSTRIDE + r * 72 + kq * 8) * 2,
                      B + (size_t)(bn0 + r) * ldb + k0 + kq * 8);
            } else {
                int kr = fid >> 4, nq = fid & 15;
                cpa16(bBase + (st * SSTRIDE + kr * 136 + nq * 8) * 2,
                      B + (size_t)(k0 + kr) * ldb + bn0 + nq * 8);
            }
        }
    };

    // fragment loader for one k16 sub-step
    uint32_t fa[2][4][4], fbr[2][2][4];
    auto ldfrags = [&](uint32_t aS, uint32_t bS, int kc, int pb) {
        const int kk = kc * 16;
#pragma unroll
        for (int mf = 0; mf < 4; mf++) {
            uint32_t a = aS + ((wm + mf * 16 + arow) * 72 + acol + kk) * 2;
            asm volatile("ldmatrix.sync.aligned.m8n8.x4.shared.b16 {%0,%1,%2,%3},[%4];"
                : "=r"(fa[pb][mf][0]), "=r"(fa[pb][mf][1]),
                  "=r"(fa[pb][mf][2]), "=r"(fa[pb][mf][3])
                : "r"(a));
        }
#pragma unroll
        for (int nfp = 0; nfp < 2; nfp++) {
            if (BKMAJ) {
                uint32_t a = bS + ((wn + nfp * 16 + bt_row) * 72 + kk + bt_col) * 2;
                asm volatile("ldmatrix.sync.aligned.m8n8.x4.shared.b16 {%0,%1,%2,%3},[%4];"
                    : "=r"(fbr[pb][nfp][0]), "=r"(fbr[pb][nfp][1]),
                      "=r"(fbr[pb][nfp][2]), "=r"(fbr[pb][nfp][3])
                    : "r"(a));
            } else {
                uint32_t a = bS + ((kk + bf_row) * 136 + wn + nfp * 16 + bf_col) * 2;
                asm volatile("ldmatrix.sync.aligned.m8n8.x4.trans.shared.b16 {%0,%1,%2,%3},[%4];"
                    : "=r"(fbr[pb][nfp][0]), "=r"(fbr[pb][nfp][1]),
                      "=r"(fbr[pb][nfp][2]), "=r"(fbr[pb][nfp][3])
                    : "r"(a));
            }
        }
    };

    // prologue: fill stages 0..1
#pragma unroll
    for (int st = 0; st < STAGES - 1; st++) {
        fillA(st, st * BK); fillB(st, st * BK);
        cpa_commit();
    }

    int buf = 0, fb = STAGES - 1;
    for (int kt = 0; kt < nK; kt++) {
        cpa_wait<STAGES - 2>();
        __syncthreads();

        const uint32_t aS = aBase + buf * SSTRIDE * 2;
        const uint32_t bS = bBase + buf * SSTRIDE * 2;

        // head fragments first (critical path), then early gmem fill
        ldfrags(aS, bS, 0, 0);

        const int kf = kt + STAGES - 1;
        if (kf < nK) { fillA(fb, kf * BK); fillB(fb, kf * BK); }
        cpa_commit();

#pragma unroll
        for (int kc = 0; kc < 4; kc++) {
            const int cur = kc & 1;
            if (kc < 3) ldfrags(aS, bS, kc + 1, cur ^ 1);   // overlap with HMMAs below
#pragma unroll
            for (int mf = 0; mf < 4; mf++)
#pragma unroll
                for (int nf = 0; nf < 4; nf++) {
                    asm volatile(
                        "mma.sync.aligned.m16n8k16.row.col.f32.bf16.bf16.f32 "
                        "{%0,%1,%2,%3},{%4,%5,%6,%7},{%8,%9},{%0,%1,%2,%3};"
                        : "+f"(c[mf][nf][0]), "+f"(c[mf][nf][1]),
                          "+f"(c[mf][nf][2]), "+f"(c[mf][nf][3])
                        : "r"(fa[cur][mf][0]), "r"(fa[cur][mf][1]),
                          "r"(fa[cur][mf][2]), "r"(fa[cur][mf][3]),
                          "r"(fbr[cur][nf >> 1][(nf & 1) * 2]),
                          "r"(fbr[cur][nf >> 1][(nf & 1) * 2 + 1]));
                }
        }

        buf = (buf + 1 == STAGES) ? 0 : buf + 1;
        fb  = (fb  + 1 == STAGES) ? 0 : fb  + 1;
    }

    // epilogue
    if (EPI == 2) {
        __nv_bfloat16* C = (__nv_bfloat16*)Cv + (long)blockIdx.z * sC;
#pragma unroll
        for (int mf = 0; mf < 4; mf++) {
            const int r0 = bm0 + wm + mf * 16 + gid;
#pragma unroll
            for (int nf = 0; nf < 4; nf++) {
                const int cc = bn0 + wn + nf * 8 + tig * 2;
                __nv_bfloat162 v0 = __float22bfloat162_rn(make_float2(c[mf][nf][0], c[mf][nf][1]));
                __nv_bfloat162 v1 = __float22bfloat162_rn(make_float2(c[mf][nf][2], c[mf][nf][3]));
                *reinterpret_cast<__nv_bfloat162*>(C + (size_t)r0 * ldc + cc) = v0;
                *reinterpret_cast<__nv_bfloat162*>(C + (size_t)(r0 + 8) * ldc + cc) = v1;
            }
        }
    } else {
        float* C = (float*)Cv + (long)blockIdx.z * sC;
#pragma unroll
        for (int mf = 0; mf < 4; mf++) {
            const int r0 = bm0 + wm + mf * 16 + gid;
#pragma unroll
            for (int nf = 0; nf < 4; nf++) {
                const int cc = bn0 + wn + nf * 8 + tig * 2;
                float2 v0 = make_float2(c[mf][nf][0], c[mf][nf][1]);
                float2 v1 = make_float2(c[mf][nf][2], c[mf][nf][3]);
                if (EPI == 1) {
                    const float2 q0 = *reinterpret_cast<const float2*>(R + (size_t)r0 * ldr + cc);
                    const float2 q1 = *reinterpret_cast<const float2*>(R + (size_t)(r0 + 8) * ldr + cc);
                    v0.x += q0.x; v0.y += q0.y;
                    v1.x += q1.x; v1.y += q1.y;
                }
                *reinterpret_cast<float2*>(C + (size_t)r0 * ldc + cc) = v0;
                *reinterpret_cast<float2*>(C + (size_t)(r0 + 8) * ldc + cc) = v1;
            }
        }
    }
}

// ---------------- launch ------------------------------------------------------
extern "C" void kernel_launch(void* const* d_in, const int* in_sizes, int n_in,
                              void* d_out, int out_size) {
    const float* x     = (const float*)d_in[0];
    const float* qkvw  = (const float*)d_in[1];
    const float* ow    = (const float*)d_in[2];
    const float* gamma = (const float*)d_in[3];
    const float* beta  = (const float*)d_in[4];
    float* out = (float*)d_out;

    __nv_bfloat16 *xn, *wqkv, *wo, *qkv, *pr, *av;
    float *sc;
    cudaGetSymbolAddress((void**)&xn,   g_xn);
    cudaGetSymbolAddress((void**)&wqkv, g_wqkv);
    cudaGetSymbolAddress((void**)&wo,   g_wo);
    cudaGetSymbolAddress((void**)&qkv,  g_qkv);
    cudaGetSymbolAddress((void**)&sc,   g_sc);
    cudaGetSymbolAddress((void**)&pr,   g_pr);
    cudaGetSymbolAddress((void**)&av,   g_av);

    cudaFuncSetAttribute(gemm_bf16<false, 2, false, false>,
                         cudaFuncAttributeMaxDynamicSharedMemorySize, SMEM_BYTES);
    cudaFuncSetAttribute(gemm_bf16<true,  0, true,  false>,
                         cudaFuncAttributeMaxDynamicSharedMemorySize, SMEM_BYTES);
    cudaFuncSetAttribute(gemm_bf16<false, 2, false, true>,
                         cudaFuncAttributeMaxDynamicSharedMemorySize, SMEM_BYTES);
    cudaFuncSetAttribute(gemm_bf16<false, 1, false, false>,
                         cudaFuncAttributeMaxDynamicSharedMemorySize, SMEM_BYTES);

    const int ROWS = BATCH * SEQ;  // 8192
    const long sQKV = (long)SEQ * NQKV;
    const long sSS  = (long)SEQ * SEQ;
    const long sSH  = (long)SEQ * HID;

    // 1) convert weights to bf16
    cvt_kernel<<<(HID * NQKV / 4 + 255) / 256, 256>>>(
        (const float4*)qkvw, (uint32_t*)wqkv, HID * NQKV / 4);
    cvt_kernel<<<(HID * HID / 4 + 255) / 256, 256>>>(
        (const float4*)ow, (uint32_t*)wo, HID * HID / 4);

    // 2) LayerNorm -> bf16
    ln_kernel<<<ROWS, 256>>>(x, gamma, beta, xn);

    // 3) QKV projection: [8192,2048] @ [2048,6144] -> bf16
    gemm_bf16<false, 2, false, false><<<dim3(NQKV / 128, ROWS / 128, 1), 256, SMEM_BYTES>>>(
        xn, HID, 0, wqkv, NQKV, 0, qkv, NQKV, 0, HID, nullptr, 0);

    // 4) scores = Q @ K^T per batch (skip fully-masked blocks) -> fp32
    gemm_bf16<true, 0, true, false><<<dim3(SEQ / 128, SEQ / 128, BATCH), 256, SMEM_BYTES>>>(
        qkv, NQKV, sQKV, qkv + HID, NQKV, sQKV, sc, SEQ, sSS, HID, nullptr, 0);

    // 5) causal softmax (scale fused) -> bf16 probs, zeroed to diag block edge
    softmax_kernel<<<ROWS, 256>>>(sc, pr, 1.0f / sqrtf((float)HID));

    // 6) attn @ V per batch (K-loop clipped at diagonal) -> bf16
    gemm_bf16<false, 2, false, true><<<dim3(HID / 128, SEQ / 128, BATCH), 256, SMEM_BYTES>>>(
        pr, SEQ, sSS, qkv + 2 * HID, NQKV, sQKV, av, HID, sSH, SEQ, nullptr, 0);

    // 7) O projection + residual: [8192,2048] @ [2048,2048] + x -> fp32 out
    gemm_bf16<false, 1, false, false><<<dim3(HID / 128, ROWS / 128, 1), 256, SMEM_BYTES>>>(
        av, HID, 0, wo, HID, 0, out, HID, 0, HID, x, HID);
}

// round 9
// speedup vs baseline: 1.0146x; 1.0146x over previous
#include <cuda_runtime.h>
#include <cuda_bf16.h>
#include <cstdint>
#include <math.h>

#define HID  2048
#define SEQ  2048
#define BATCH 4
#define NQKV 6144   // 3*HID

#define STAGES 3
#define BK 64
#define SSTRIDE 9216          // bf16 elems per operand per stage (128*72)
#define SMEM_BYTES (2 * STAGES * SSTRIDE * 2)   // 110592

// ---------------- scratch (device globals; no allocations allowed) ----------
__device__ __align__(16) __nv_bfloat16 g_xn  [BATCH * SEQ * HID];    // 32 MB
__device__ __align__(16) __nv_bfloat16 g_wqkv[HID * NQKV];           // 24 MB
__device__ __align__(16) __nv_bfloat16 g_wo  [HID * HID];            //  8 MB
__device__ __align__(16) __nv_bfloat16 g_qkv [BATCH * SEQ * NQKV];   // 96 MB
__device__ __align__(16) float         g_sc  [BATCH * SEQ * SEQ];    // 64 MB
__device__ __align__(16) __nv_bfloat16 g_pr  [BATCH * SEQ * SEQ];    // 32 MB
__device__ __align__(16) __nv_bfloat16 g_av  [BATCH * SEQ * HID];    // 32 MB

// ---------------- helpers ----------------------------------------------------
__device__ __forceinline__ void cpa16(uint32_t dst, const void* src) {
    asm volatile("cp.async.cg.shared.global [%0], [%1], 16;" :: "r"(dst), "l"(src));
}
__device__ __forceinline__ void cpa_commit() {
    asm volatile("cp.async.commit_group;");
}
template <int N>
__device__ __forceinline__ void cpa_wait() {
    asm volatile("cp.async.wait_group %0;" :: "n"(N));
}

// ---------------- fp32 -> bf16 convert (both weight tensors, one launch) -----
__global__ void cvt2_kernel(const float4* __restrict__ in1, uint32_t* __restrict__ out1, int n41,
                            const float4* __restrict__ in2, uint32_t* __restrict__ out2, int n42) {
    int i = blockIdx.x * blockDim.x + threadIdx.x;
    const float4* in; uint32_t* out;
    if (i < n41) { in = in1; out = out1; }
    else if (i < n41 + n42) { in = in2 - n41; out = out2 - (size_t)n41 * 2; }
    else return;
    float4 v = in[i];
    __nv_bfloat162 a = __float22bfloat162_rn(make_float2(v.x, v.y));
    __nv_bfloat162 b = __float22bfloat162_rn(make_float2(v.z, v.w));
    out[(size_t)i * 2 + 0] = *reinterpret_cast<uint32_t*>(&a);
    out[(size_t)i * 2 + 1] = *reinterpret_cast<uint32_t*>(&b);
}

// ---------------- LayerNorm: one block per row, bf16 out ---------------------
__global__ void ln_kernel(const float* __restrict__ x,
                          const float* __restrict__ gamma,
                          const float* __restrict__ beta,
                          __nv_bfloat16* __restrict__ out) {
    const int row = blockIdx.x;
    const float* xr = x + (size_t)row * HID;
    __nv_bfloat16* orow = out + (size_t)row * HID;
    const int tid = threadIdx.x;

    float v[8];
    float s = 0.f, s2 = 0.f;
#pragma unroll
    for (int i = 0; i < 8; i++) {
        float val = xr[tid + i * 256];
        v[i] = val; s += val; s2 += val * val;
    }
    __shared__ float red[2][8];
#pragma unroll
    for (int o = 16; o > 0; o >>= 1) {
        s  += __shfl_down_sync(0xffffffffu, s,  o);
        s2 += __shfl_down_sync(0xffffffffu, s2, o);
    }
    const int w = tid >> 5, l = tid & 31;
    if (l == 0) { red[0][w] = s; red[1][w] = s2; }
    __syncthreads();
    if (w == 0) {
        float a  = red[0][l & 7];
        float b2 = red[1][l & 7];
#pragma unroll
        for (int o = 4; o > 0; o >>= 1) {
            a  += __shfl_down_sync(0xffffffffu, a,  o);
            b2 += __shfl_down_sync(0xffffffffu, b2, o);
        }
        if (l == 0) { red[0][0] = a; red[1][0] = b2; }
    }
    __syncthreads();
    const float mean = red[0][0] * (1.f / HID);
    const float var  = red[1][0] * (1.f / HID) - mean * mean;
    const float rstd = rsqrtf(var + 1e-5f);
#pragma unroll
    for (int i = 0; i < 8; i++) {
        int h = tid + i * 256;
        orow[h] = __float2bfloat16((v[i] - mean) * rstd * gamma[h] + beta[h]);
    }
}

// ---------------- causal softmax: single-pass, row in registers --------------
// fp32 scores in, bf16 probs out. Zeroes only to the 128-aligned diagonal edge.
__global__ void softmax_kernel(const float* __restrict__ sc,
                               __nv_bfloat16* __restrict__ pr, float scale) {
    const int row = blockIdx.x;            // b*SEQ + q
    const int q = row & (SEQ - 1);
    const float* p = sc + (size_t)row * SEQ;
    __nv_bfloat16* po = pr + (size_t)row * SEQ;
    const int n = q + 1;
    const int nend = ((q >> 7) + 1) << 7;  // PV reads only [0, nend)
    const int tid = threadIdx.x;
    __shared__ float red[8];

    // load the active row segment into registers (<= 8 per thread)
    float v[8];
    float mx = -1e30f;
    int cnt = 0;
#pragma unroll
    for (int i = 0; i < 8; i++) {
        int t = tid + i * 256;
        if (t < n) {
            float val = p[t] * scale;
            v[i] = val;
            mx = fmaxf(mx, val);
            cnt = i + 1;
        }
    }
#pragma unroll
    for (int o = 16; o > 0; o >>= 1) mx = fmaxf(mx, __shfl_down_sync(0xffffffffu, mx, o));
    if ((tid & 31) == 0) red[tid >> 5] = mx;
    __syncthreads();
    if (tid < 32) {
        float a = red[tid & 7];
#pragma unroll
        for (int o = 4; o > 0; o >>= 1) a = fmaxf(a, __shfl_down_sync(0xffffffffu, a, o));
        if (tid == 0) red[0] = a;
    }
    __syncthreads();
    mx = red[0];
    __syncthreads();

    float sum = 0.f;
#pragma unroll
    for (int i = 0; i < 8; i++) {
        if (i < cnt) {
            float e = __expf(v[i] - mx);
            v[i] = e;
            sum += e;
        }
    }
#pragma unroll
    for (int o = 16; o > 0; o >>= 1) sum += __shfl_down_sync(0xffffffffu, sum, o);
    if ((tid & 31) == 0) red[tid >> 5] = sum;
    __syncthreads();
    if (tid < 32) {
        float a = red[tid & 7];
#pragma unroll
        for (int o = 4; o > 0; o >>= 1) a += __shfl_down_sync(0xffffffffu, a, o);
        if (tid == 0) red[0] = a;
    }
    __syncthreads();
    const float inv = 1.f / red[0];
#pragma unroll
    for (int i = 0; i < 8; i++) {
        int t = tid + i * 256;
        if (i < cnt) po[t] = __float2bfloat16(v[i] * inv);
        else if (t < nend) po[t] = __float2bfloat16(0.f);
    }
}

// ---------------- bf16 tensor-core GEMM (3-stage, BK=64) ---------------------
// C[M,N] = A[M,K] @ B. A row-major bf16 (lda).
// BKMAJ=true:  B stored [N,K] k-contig (ldb) -> A @ B^T.
// BKMAJ=false: B stored [K,N] n-contig (ldb).
// EPI: 0 = fp32 out, 1 = fp32 out + residual R, 2 = bf16 out.
// CKLIM also reverses mb order (heavy diagonal blocks scheduled first).
// Block 128x128x64, 8 warps of 64x32, m16n8k16 bf16 mma, 2 CTAs/SM.
template <bool BKMAJ, int EPI, bool CSKIP, bool CKLIM>
__global__ void __launch_bounds__(256, 2)
gemm_bf16(const __nv_bfloat16* __restrict__ A, int lda, long sA,
          const __nv_bfloat16* __restrict__ B, int ldb, long sB,
          void* __restrict__ Cv, int ldc, long sC,
          int Kdim,
          const float* __restrict__ R, int ldr) {
    const int mb = CKLIM ? (gridDim.y - 1 - blockIdx.y) : blockIdx.y;
    const int nb = blockIdx.x;
    if (CSKIP && nb > mb) return;   // fully-masked upper-triangular score block

    A += (long)blockIdx.z * sA;
    B += (long)blockIdx.z * sB;

    const int kend = CKLIM ? min(Kdim, (mb + 1) * 128) : Kdim;
    const int nK = kend >> 6;   // BK = 64; >= 2 for all our shapes

    extern __shared__ __align__(16) __nv_bfloat16 sm[];
    // A stages: sm[st*SSTRIDE], layout [128 rows][72]   (64 k + pad 8)
    // B stages: sm[STAGES*SSTRIDE + st*SSTRIDE],
    //           BKMAJ ? [128 n][72 k] : [64 k][136 n]
    const uint32_t smBase = (uint32_t)__cvta_generic_to_shared(sm);
    const uint32_t aBase = smBase;
    const uint32_t bBase = smBase + STAGES * SSTRIDE * 2;

    const int tid = threadIdx.x;
    const int warp = tid >> 5, lane = tid & 31;
    const int gid = lane >> 2, tig = lane & 3;
    const int wm = (warp & 1) * 64, wn = (warp >> 1) * 32;
    const int bm0 = mb * 128, bn0 = nb * 128;

    float c[4][4][4];
#pragma unroll
    for (int i = 0; i < 4; i++)
#pragma unroll
        for (int j = 0; j < 4; j++)
#pragma unroll
            for (int k = 0; k < 4; k++) c[i][j][k] = 0.f;

    // ldmatrix per-lane coordinates
    const int arow = (lane & 7) + ((lane >> 3) & 1) * 8;
    const int acol = ((lane >> 4) & 1) * 8;
    const int ln8 = lane & 7, sel = lane >> 3;
    const int bt_row = ((sel >> 1) & 1) * 8 + ln8;   // BKMAJ=true: n within 16
    const int bt_col = (sel & 1) * 8;                // k-half
    const int bf_row = (sel & 1) * 8 + ln8;          // BKMAJ=false: k within 16
    const int bf_col = ((sel >> 1) & 1) * 8;         // n within 16

    auto fillA = [&](int st, int k0) {
#pragma unroll
        for (int p = 0; p < 4; p++) {
            int fid = tid + p * 256;
            int r = fid >> 3, kq = fid & 7;
            cpa16(aBase + (st * SSTRIDE + r * 72 + kq * 8) * 2,
                  A + (size_t)(bm0 + r) * lda + k0 + kq * 8);
        }
    };
    auto fillB = [&](int st, int k0) {
#pragma unroll
        for (int p = 0; p < 4; p++) {
            int fid = tid + p * 256;
            if (BKMAJ) {
                int r = fid >> 3, kq = fid & 7;
                cpa16(bBase + (st * SSTRIDE + r * 72 + kq * 8) * 2,
                      B + (size_t)(bn0 + r) * ldb + k0 + kq * 8);
            } else {
                int kr = fid >> 4, nq = fid & 15;
                cpa16(bBase + (st * SSTRIDE + kr * 136 + nq * 8) * 2,
                      B + (size_t)(k0 + kr) * ldb + bn0 + nq * 8);
            }
        }
    };

    // prologue: fill stages 0..1
#pragma unroll
    for (int st = 0; st < STAGES - 1; st++) {
        fillA(st, st * BK); fillB(st, st * BK);
        cpa_commit();
    }

    int buf = 0, fb = STAGES - 1;
    for (int kt = 0; kt < nK; kt++) {
        cpa_wait<STAGES - 2>();
        __syncthreads();

        // EARLY fill: start stage kt+2's copies before this iter's MMA work.
        const int kf = kt + STAGES - 1;
        if (kf < nK) { fillA(fb, kf * BK); fillB(fb, kf * BK); }
        cpa_commit();

        const uint32_t aS = aBase + buf * SSTRIDE * 2;
        const uint32_t bS = bBase + buf * SSTRIDE * 2;

#pragma unroll
        for (int kc = 0; kc < 4; kc++) {
            const int kk = kc * 16;
            uint32_t af[4][4], bfr[2][4];
#pragma unroll
            for (int mf = 0; mf < 4; mf++) {
                uint32_t a = aS + ((wm + mf * 16 + arow) * 72 + acol + kk) * 2;
                asm volatile("ldmatrix.sync.aligned.m8n8.x4.shared.b16 {%0,%1,%2,%3},[%4];"
                    : "=r"(af[mf][0]), "=r"(af[mf][1]), "=r"(af[mf][2]), "=r"(af[mf][3])
                    : "r"(a));
            }
#pragma unroll
            for (int nfp = 0; nfp < 2; nfp++) {
                if (BKMAJ) {
                    uint32_t a = bS + ((wn + nfp * 16 + bt_row) * 72 + kk + bt_col) * 2;
                    asm volatile("ldmatrix.sync.aligned.m8n8.x4.shared.b16 {%0,%1,%2,%3},[%4];"
                        : "=r"(bfr[nfp][0]), "=r"(bfr[nfp][1]),
                          "=r"(bfr[nfp][2]), "=r"(bfr[nfp][3])
                        : "r"(a));
                } else {
                    uint32_t a = bS + ((kk + bf_row) * 136 + wn + nfp * 16 + bf_col) * 2;
                    asm volatile("ldmatrix.sync.aligned.m8n8.x4.trans.shared.b16 {%0,%1,%2,%3},[%4];"
                        : "=r"(bfr[nfp][0]), "=r"(bfr[nfp][1]),
                          "=r"(bfr[nfp][2]), "=r"(bfr[nfp][3])
                        : "r"(a));
                }
            }
#pragma unroll
            for (int mf = 0; mf < 4; mf++)
#pragma unroll
                for (int nf = 0; nf < 4; nf++) {
                    asm volatile(
                        "mma.sync.aligned.m16n8k16.row.col.f32.bf16.bf16.f32 "
                        "{%0,%1,%2,%3},{%4,%5,%6,%7},{%8,%9},{%0,%1,%2,%3};"
                        : "+f"(c[mf][nf][0]), "+f"(c[mf][nf][1]),
                          "+f"(c[mf][nf][2]), "+f"(c[mf][nf][3])
                        : "r"(af[mf][0]), "r"(af[mf][1]), "r"(af[mf][2]), "r"(af[mf][3]),
                          "r"(bfr[nf >> 1][(nf & 1) * 2]), "r"(bfr[nf >> 1][(nf & 1) * 2 + 1]));
                }
        }

        buf = (buf + 1 == STAGES) ? 0 : buf + 1;
        fb  = (fb  + 1 == STAGES) ? 0 : fb  + 1;
    }

    // epilogue
    if (EPI == 2) {
        __nv_bfloat16* C = (__nv_bfloat16*)Cv + (long)blockIdx.z * sC;
#pragma unroll
        for (int mf = 0; mf < 4; mf++) {
            const int r0 = bm0 + wm + mf * 16 + gid;
#pragma unroll
            for (int nf = 0; nf < 4; nf++) {
                const int cc = bn0 + wn + nf * 8 + tig * 2;
                __nv_bfloat162 v0 = __float22bfloat162_rn(make_float2(c[mf][nf][0], c[mf][nf][1]));
                __nv_bfloat162 v1 = __float22bfloat162_rn(make_float2(c[mf][nf][2], c[mf][nf][3]));
                *reinterpret_cast<__nv_bfloat162*>(C + (size_t)r0 * ldc + cc) = v0;
                *reinterpret_cast<__nv_bfloat162*>(C + (size_t)(r0 + 8) * ldc + cc) = v1;
            }
        }
    } else {
        float* C = (float*)Cv + (long)blockIdx.z * sC;
#pragma unroll
        for (int mf = 0; mf < 4; mf++) {
            const int r0 = bm0 + wm + mf * 16 + gid;
#pragma unroll
            for (int nf = 0; nf < 4; nf++) {
                const int cc = bn0 + wn + nf * 8 + tig * 2;
                float2 v0 = make_float2(c[mf][nf][0], c[mf][nf][1]);
                float2 v1 = make_float2(c[mf][nf][2], c[mf][nf][3]);
                if (EPI == 1) {
                    const float2 q0 = *reinterpret_cast<const float2*>(R + (size_t)r0 * ldr + cc);
                    const float2 q1 = *reinterpret_cast<const float2*>(R + (size_t)(r0 + 8) * ldr + cc);
                    v0.x += q0.x; v0.y += q0.y;
                    v1.x += q1.x; v1.y += q1.y;
                }
                *reinterpret_cast<float2*>(C + (size_t)r0 * ldc + cc) = v0;
                *reinterpret_cast<float2*>(C + (size_t)(r0 + 8) * ldc + cc) = v1;
            }
        }
    }
}

// ---------------- launch ------------------------------------------------------
extern "C" void kernel_launch(void* const* d_in, const int* in_sizes, int n_in,
                              void* d_out, int out_size) {
    const float* x     = (const float*)d_in[0];
    const float* qkvw  = (const float*)d_in[1];
    const float* ow    = (const float*)d_in[2];
    const float* gamma = (const float*)d_in[3];
    const float* beta  = (const float*)d_in[4];
    float* out = (float*)d_out;

    __nv_bfloat16 *xn, *wqkv, *wo, *qkv, *pr, *av;
    float *sc;
    cudaGetSymbolAddress((void**)&xn,   g_xn);
    cudaGetSymbolAddress((void**)&wqkv, g_wqkv);
    cudaGetSymbolAddress((void**)&wo,   g_wo);
    cudaGetSymbolAddress((void**)&qkv,  g_qkv);
    cudaGetSymbolAddress((void**)&sc,   g_sc);
    cudaGetSymbolAddress((void**)&pr,   g_pr);
    cudaGetSymbolAddress((void**)&av,   g_av);

    cudaFuncSetAttribute(gemm_bf16<false, 2, false, false>,
                         cudaFuncAttributeMaxDynamicSharedMemorySize, SMEM_BYTES);
    cudaFuncSetAttribute(gemm_bf16<true,  0, true,  false>,
                         cudaFuncAttributeMaxDynamicSharedMemorySize, SMEM_BYTES);
    cudaFuncSetAttribute(gemm_bf16<false, 2, false, true>,
                         cudaFuncAttributeMaxDynamicSharedMemorySize, SMEM_BYTES);
    cudaFuncSetAttribute(gemm_bf16<false, 1, false, false>,
                         cudaFuncAttributeMaxDynamicSharedMemorySize, SMEM_BYTES);

    const int ROWS = BATCH * SEQ;  // 8192
    const long sQKV = (long)SEQ * NQKV;
    const long sSS  = (long)SEQ * SEQ;
    const long sSH  = (long)SEQ * HID;

    // 1) convert both weight tensors to bf16 (one launch)
    const int n41 = HID * NQKV / 4, n42 = HID * HID / 4;
    cvt2_kernel<<<(n41 + n42 + 255) / 256, 256>>>(
        (const float4*)qkvw, (uint32_t*)wqkv, n41,
        (const float4*)ow,   (uint32_t*)wo,   n42);

    // 2) LayerNorm -> bf16
    ln_kernel<<<ROWS, 256>>>(x, gamma, beta, xn);

    // 3) QKV projection: [8192,2048] @ [2048,6144] -> bf16
    gemm_bf16<false, 2, false, false><<<dim3(NQKV / 128, ROWS / 128, 1), 256, SMEM_BYTES>>>(
        xn, HID, 0, wqkv, NQKV, 0, qkv, NQKV, 0, HID, nullptr, 0);

    // 4) scores = Q @ K^T per batch (skip fully-masked blocks) -> fp32
    gemm_bf16<true, 0, true, false><<<dim3(SEQ / 128, SEQ / 128, BATCH), 256, SMEM_BYTES>>>(
        qkv, NQKV, sQKV, qkv + HID, NQKV, sQKV, sc, SEQ, sSS, HID, nullptr, 0);

    // 5) causal softmax, single-pass in registers -> bf16 probs
    softmax_kernel<<<ROWS, 256>>>(sc, pr, 1.0f / sqrtf((float)HID));

    // 6) attn @ V per batch (K clipped at diagonal; heavy blocks first) -> bf16
    gemm_bf16<false, 2, false, true><<<dim3(HID / 128, SEQ / 128, BATCH), 256, SMEM_BYTES>>>(
        pr, SEQ, sSS, qkv + 2 * HID, NQKV, sQKV, av, HID, sSH, SEQ, nullptr, 0);

    // 7) O projection + residual: [8192,2048] @ [2048,2048] + x -> fp32 out
    gemm_bf16<false, 1, false, false><<<dim3(HID / 128, ROWS / 128, 1), 256, SMEM_BYTES>>>(
        av, HID, 0, wo, HID, 0, out, HID, 0, HID, x, HID);
}

// round 10
// speedup vs baseline: 1.0173x; 1.0027x over previous
#include <cuda_runtime.h>
#include <cuda_bf16.h>
#include <cstdint>
#include <math.h>

#define HID  2048
#define SEQ  2048
#define BATCH 4
#define NQKV 6144   // 3*HID

#define STAGES 3
#define BK 64
#define SSTRIDE 9216          // bf16 elems per operand per stage (128*72)
#define SMEM_BYTES (2 * STAGES * SSTRIDE * 2)   // 110592

// ---------------- scratch (device globals; no allocations allowed) ----------
__device__ __align__(16) __nv_bfloat16 g_xn  [BATCH * SEQ * HID];    // 32 MB
__device__ __align__(16) __nv_bfloat16 g_wqkv[HID * NQKV];           // 24 MB
__device__ __align__(16) __nv_bfloat16 g_wo  [HID * HID];            //  8 MB
__device__ __align__(16) __nv_bfloat16 g_qkv [BATCH * SEQ * NQKV];   // 96 MB
__device__ __align__(16) float         g_sc  [BATCH * SEQ * SEQ];    // 64 MB
__device__ __align__(16) __nv_bfloat16 g_pr  [BATCH * SEQ * SEQ];    // 32 MB
__device__ __align__(16) __nv_bfloat16 g_av  [BATCH * SEQ * HID];    // 32 MB

// ---------------- helpers ----------------------------------------------------
__device__ __forceinline__ void cpa16(uint32_t dst, const void* src) {
    asm volatile("cp.async.cg.shared.global [%0], [%1], 16;" :: "r"(dst), "l"(src));
}
__device__ __forceinline__ void cpa_commit() {
    asm volatile("cp.async.commit_group;");
}
template <int N>
__device__ __forceinline__ void cpa_wait() {
    asm volatile("cp.async.wait_group %0;" :: "n"(N));
}

// ---------------- fused prep: weight converts + LayerNorm --------------------
// blocks [0, nCvt)                : fp32->bf16 convert of both weight tensors
// blocks [nCvt, nCvt + BATCH*SEQ) : LayerNorm rows -> bf16
__global__ void prep_kernel(const float4* __restrict__ w1, uint32_t* __restrict__ o1, int n41,
                            const float4* __restrict__ w2, uint32_t* __restrict__ o2, int n42,
                            int nCvt,
                            const float* __restrict__ x,
                            const float* __restrict__ gamma,
                            const float* __restrict__ beta,
                            __nv_bfloat16* __restrict__ xn) {
    if (blockIdx.x < (unsigned)nCvt) {
        int i = blockIdx.x * blockDim.x + threadIdx.x;
        const float4* in; uint32_t* out;
        if (i < n41) { in = w1; out = o1; }
        else if (i < n41 + n42) { in = w2 - n41; out = o2 - (size_t)n41 * 2; }
        else return;
        float4 v = in[i];
        __nv_bfloat162 a = __float22bfloat162_rn(make_float2(v.x, v.y));
        __nv_bfloat162 b = __float22bfloat162_rn(make_float2(v.z, v.w));
        out[(size_t)i * 2 + 0] = *reinterpret_cast<uint32_t*>(&a);
        out[(size_t)i * 2 + 1] = *reinterpret_cast<uint32_t*>(&b);
        return;
    }

    const int row = blockIdx.x - nCvt;
    const float* xr = x + (size_t)row * HID;
    __nv_bfloat16* orow = xn + (size_t)row * HID;
    const int tid = threadIdx.x;

    float v[8];
    float s = 0.f, s2 = 0.f;
#pragma unroll
    for (int i = 0; i < 8; i++) {
        float val = xr[tid + i * 256];
        v[i] = val; s += val; s2 += val * val;
    }
    __shared__ float red[2][8];
#pragma unroll
    for (int o = 16; o > 0; o >>= 1) {
        s  += __shfl_down_sync(0xffffffffu, s,  o);
        s2 += __shfl_down_sync(0xffffffffu, s2, o);
    }
    const int w = tid >> 5, l = tid & 31;
    if (l == 0) { red[0][w] = s; red[1][w] = s2; }
    __syncthreads();
    if (w == 0) {
        float a  = red[0][l & 7];
        float b2 = red[1][l & 7];
#pragma unroll
        for (int o = 4; o > 0; o >>= 1) {
            a  += __shfl_down_sync(0xffffffffu, a,  o);
            b2 += __shfl_down_sync(0xffffffffu, b2, o);
        }
        if (l == 0) { red[0][0] = a; red[1][0] = b2; }
    }
    __syncthreads();
    const float mean = red[0][0] * (1.f / HID);
    const float var  = red[1][0] * (1.f / HID) - mean * mean;
    const float rstd = rsqrtf(var + 1e-5f);
#pragma unroll
    for (int i = 0; i < 8; i++) {
        int h = tid + i * 256;
        orow[h] = __float2bfloat16((v[i] - mean) * rstd * gamma[h] + beta[h]);
    }
}

// ---------------- causal softmax: single-pass, row in registers --------------
// fp32 scores in, bf16 probs out. Zeroes only to the 128-aligned diagonal edge.
__global__ void softmax_kernel(const float* __restrict__ sc,
                               __nv_bfloat16* __restrict__ pr, float scale) {
    const int row = blockIdx.x;            // b*SEQ + q
    const int q = row & (SEQ - 1);
    const float* p = sc + (size_t)row * SEQ;
    __nv_bfloat16* po = pr + (size_t)row * SEQ;
    const int n = q + 1;
    const int nend = ((q >> 7) + 1) << 7;  // PV reads only [0, nend)
    const int tid = threadIdx.x;
    __shared__ float red[8];

    float v[8];
    float mx = -1e30f;
    int cnt = 0;
#pragma unroll
    for (int i = 0; i < 8; i++) {
        int t = tid + i * 256;
        if (t < n) {
            float val = p[t] * scale;
            v[i] = val;
            mx = fmaxf(mx, val);
            cnt = i + 1;
        }
    }
#pragma unroll
    for (int o = 16; o > 0; o >>= 1) mx = fmaxf(mx, __shfl_down_sync(0xffffffffu, mx, o));
    if ((tid & 31) == 0) red[tid >> 5] = mx;
    __syncthreads();
    if (tid < 32) {
        float a = red[tid & 7];
#pragma unroll
        for (int o = 4; o > 0; o >>= 1) a = fmaxf(a, __shfl_down_sync(0xffffffffu, a, o));
        if (tid == 0) red[0] = a;
    }
    __syncthreads();
    mx = red[0];
    __syncthreads();

    float sum = 0.f;
#pragma unroll
    for (int i = 0; i < 8; i++) {
        if (i < cnt) {
            float e = __expf(v[i] - mx);
            v[i] = e;
            sum += e;
        }
    }
#pragma unroll
    for (int o = 16; o > 0; o >>= 1) sum += __shfl_down_sync(0xffffffffu, sum, o);
    if ((tid & 31) == 0) red[tid >> 5] = sum;
    __syncthreads();
    if (tid < 32) {
        float a = red[tid & 7];
#pragma unroll
        for (int o = 4; o > 0; o >>= 1) a += __shfl_down_sync(0xffffffffu, a, o);
        if (tid == 0) red[0] = a;
    }
    __syncthreads();
    const float inv = 1.f / red[0];
#pragma unroll
    for (int i = 0; i < 8; i++) {
        int t = tid + i * 256;
        if (i < cnt) po[t] = __float2bfloat16(v[i] * inv);
        else if (t < nend) po[t] = __float2bfloat16(0.f);
    }
}

// ---------------- bf16 tensor-core GEMM (3-stage, BK=64) ---------------------
// C[M,N] = A[M,K] @ B. A row-major bf16 (lda).
// BKMAJ=true:  B stored [N,K] k-contig (ldb) -> A @ B^T.
// BKMAJ=false: B stored [K,N] n-contig (ldb).
// EPI: 0 = fp32 out, 1 = fp32 out + residual R, 2 = bf16 out.
// TRIPACK: grid.x is a packed lower-triangular (mb,nb) index.
// CKLIM: clip K at diagonal; mb order reversed (heavy blocks first).
// Block 128x128x64, 8 warps of 64x32, m16n8k16 bf16 mma, 2 CTAs/SM.
template <bool BKMAJ, int EPI, bool TRIPACK, bool CKLIM>
__global__ void __launch_bounds__(256, 2)
gemm_bf16(const __nv_bfloat16* __restrict__ A, int lda, long sA,
          const __nv_bfloat16* __restrict__ B, int ldb, long sB,
          void* __restrict__ Cv, int ldc, long sC,
          int Kdim,
          const float* __restrict__ R, int ldr) {
    int mb, nb;
    if (TRIPACK) {
        // unpack t -> (mb, nb), nb <= mb, tri(mb) <= t
        const int t = blockIdx.x;
        int m = (int)((sqrtf(8.f * t + 1.f) - 1.f) * 0.5f);
        while ((m + 1) * (m + 2) / 2 <= t) m++;   // fix float rounding
        while (m * (m + 1) / 2 > t) m--;
        mb = m;
        nb = t - m * (m + 1) / 2;
    } else {
        mb = CKLIM ? (gridDim.y - 1 - blockIdx.y) : blockIdx.y;
        nb = blockIdx.x;
    }

    A += (long)blockIdx.z * sA;
    B += (long)blockIdx.z * sB;

    const int kend = CKLIM ? min(Kdim, (mb + 1) * 128) : Kdim;
    const int nK = kend >> 6;   // BK = 64; >= 2 for all our shapes

    extern __shared__ __align__(16) __nv_bfloat16 sm[];
    // A stages: sm[st*SSTRIDE], layout [128 rows][72]   (64 k + pad 8)
    // B stages: sm[STAGES*SSTRIDE + st*SSTRIDE],
    //           BKMAJ ? [128 n][72 k] : [64 k][136 n]
    const uint32_t smBase = (uint32_t)__cvta_generic_to_shared(sm);
    const uint32_t aBase = smBase;
    const uint32_t bBase = smBase + STAGES * SSTRIDE * 2;

    const int tid = threadIdx.x;
    const int warp = tid >> 5, lane = tid & 31;
    const int gid = lane >> 2, tig = lane & 3;
    const int wm = (warp & 1) * 64, wn = (warp >> 1) * 32;
    const int bm0 = mb * 128, bn0 = nb * 128;

    float c[4][4][4];
#pragma unroll
    for (int i = 0; i < 4; i++)
#pragma unroll
        for (int j = 0; j < 4; j++)
#pragma unroll
            for (int k = 0; k < 4; k++) c[i][j][k] = 0.f;

    // ldmatrix per-lane coordinates
    const int arow = (lane & 7) + ((lane >> 3) & 1) * 8;
    const int acol = ((lane >> 4) & 1) * 8;
    const int ln8 = lane & 7, sel = lane >> 3;
    const int bt_row = ((sel >> 1) & 1) * 8 + ln8;   // BKMAJ=true: n within 16
    const int bt_col = (sel & 1) * 8;                // k-half
    const int bf_row = (sel & 1) * 8 + ln8;          // BKMAJ=false: k within 16
    const int bf_col = ((sel >> 1) & 1) * 8;         // n within 16

    auto fillA = [&](int st, int k0) {
#pragma unroll
        for (int p = 0; p < 4; p++) {
            int fid = tid + p * 256;
            int r = fid >> 3, kq = fid & 7;
            cpa16(aBase + (st * SSTRIDE + r * 72 + kq * 8) * 2,
                  A + (size_t)(bm0 + r) * lda + k0 + kq * 8);
        }
    };
    auto fillB = [&](int st, int k0) {
#pragma unroll
        for (int p = 0; p < 4; p++) {
            int fid = tid + p * 256;
            if (BKMAJ) {
                int r = fid >> 3, kq = fid & 7;
                cpa16(bBase + (st * SSTRIDE + r * 72 + kq * 8) * 2,
                      B + (size_t)(bn0 + r) * ldb + k0 + kq * 8);
            } else {
                int kr = fid >> 4, nq = fid & 15;
                cpa16(bBase + (st * SSTRIDE + kr * 136 + nq * 8) * 2,
                      B + (size_t)(k0 + kr) * ldb + bn0 + nq * 8);
            }
        }
    };

    // prologue: fill stages 0..1
#pragma unroll
    for (int st = 0; st < STAGES - 1; st++) {
        fillA(st, st * BK); fillB(st, st * BK);
        cpa_commit();
    }

    int buf = 0, fb = STAGES - 1;
    for (int kt = 0; kt < nK; kt++) {
        cpa_wait<STAGES - 2>();
        __syncthreads();

        // EARLY fill: start stage kt+2's copies before this iter's MMA work.
        const int kf = kt + STAGES - 1;
        if (kf < nK) { fillA(fb, kf * BK); fillB(fb, kf * BK); }
        cpa_commit();

        const uint32_t aS = aBase + buf * SSTRIDE * 2;
        const uint32_t bS = bBase + buf * SSTRIDE * 2;

#pragma unroll
        for (int kc = 0; kc < 4; kc++) {
            const int kk = kc * 16;
            uint32_t af[4][4], bfr[2][4];
#pragma unroll
            for (int mf = 0; mf < 4; mf++) {
                uint32_t a = aS + ((wm + mf * 16 + arow) * 72 + acol + kk) * 2;
                asm volatile("ldmatrix.sync.aligned.m8n8.x4.shared.b16 {%0,%1,%2,%3},[%4];"
                    : "=r"(af[mf][0]), "=r"(af[mf][1]), "=r"(af[mf][2]), "=r"(af[mf][3])
                    : "r"(a));
            }
#pragma unroll
            for (int nfp = 0; nfp < 2; nfp++) {
                if (BKMAJ) {
                    uint32_t a = bS + ((wn + nfp * 16 + bt_row) * 72 + kk + bt_col) * 2;
                    asm volatile("ldmatrix.sync.aligned.m8n8.x4.shared.b16 {%0,%1,%2,%3},[%4];"
                        : "=r"(bfr[nfp][0]), "=r"(bfr[nfp][1]),
                          "=r"(bfr[nfp][2]), "=r"(bfr[nfp][3])
                        : "r"(a));
                } else {
                    uint32_t a = bS + ((kk + bf_row) * 136 + wn + nfp * 16 + bf_col) * 2;
                    asm volatile("ldmatrix.sync.aligned.m8n8.x4.trans.shared.b16 {%0,%1,%2,%3},[%4];"
                        : "=r"(bfr[nfp][0]), "=r"(bfr[nfp][1]),
                          "=r"(bfr[nfp][2]), "=r"(bfr[nfp][3])
                        : "r"(a));
                }
            }
#pragma unroll
            for (int mf = 0; mf < 4; mf++)
#pragma unroll
                for (int nf = 0; nf < 4; nf++) {
                    asm volatile(
                        "mma.sync.aligned.m16n8k16.row.col.f32.bf16.bf16.f32 "
                        "{%0,%1,%2,%3},{%4,%5,%6,%7},{%8,%9},{%0,%1,%2,%3};"
                        : "+f"(c[mf][nf][0]), "+f"(c[mf][nf][1]),
                          "+f"(c[mf][nf][2]), "+f"(c[mf][nf][3])
                        : "r"(af[mf][0]), "r"(af[mf][1]), "r"(af[mf][2]), "r"(af[mf][3]),
                          "r"(bfr[nf >> 1][(nf & 1) * 2]), "r"(bfr[nf >> 1][(nf & 1) * 2 + 1]));
                }
        }

        buf = (buf + 1 == STAGES) ? 0 : buf + 1;
        fb  = (fb  + 1 == STAGES) ? 0 : fb  + 1;
    }

    // epilogue
    if (EPI == 2) {
        __nv_bfloat16* C = (__nv_bfloat16*)Cv + (long)blockIdx.z * sC;
#pragma unroll
        for (int mf = 0; mf < 4; mf++) {
            const int r0 = bm0 + wm + mf * 16 + gid;
#pragma unroll
            for (int nf = 0; nf < 4; nf++) {
                const int cc = bn0 + wn + nf * 8 + tig * 2;
                __nv_bfloat162 v0 = __float22bfloat162_rn(make_float2(c[mf][nf][0], c[mf][nf][1]));
                __nv_bfloat162 v1 = __float22bfloat162_rn(make_float2(c[mf][nf][2], c[mf][nf][3]));
                *reinterpret_cast<__nv_bfloat162*>(C + (size_t)r0 * ldc + cc) = v0;
                *reinterpret_cast<__nv_bfloat162*>(C + (size_t)(r0 + 8) * ldc + cc) = v1;
            }
        }
    } else {
        float* C = (float*)Cv + (long)blockIdx.z * sC;
#pragma unroll
        for (int mf = 0; mf < 4; mf++) {
            const int r0 = bm0 + wm + mf * 16 + gid;
#pragma unroll
            for (int nf = 0; nf < 4; nf++) {
                const int cc = bn0 + wn + nf * 8 + tig * 2;
                float2 v0 = make_float2(c[mf][nf][0], c[mf][nf][1]);
                float2 v1 = make_float2(c[mf][nf][2], c[mf][nf][3]);
                if (EPI == 1) {
                    const float2 q0 = *reinterpret_cast<const float2*>(R + (size_t)r0 * ldr + cc);
                    const float2 q1 = *reinterpret_cast<const float2*>(R + (size_t)(r0 + 8) * ldr + cc);
                    v0.x += q0.x; v0.y += q0.y;
                    v1.x += q1.x; v1.y += q1.y;
                }
                *reinterpret_cast<float2*>(C + (size_t)r0 * ldc + cc) = v0;
                *reinterpret_cast<float2*>(C + (size_t)(r0 + 8) * ldc + cc) = v1;
            }
        }
    }
}

// ---------------- launch ------------------------------------------------------
extern "C" void kernel_launch(void* const* d_in, const int* in_sizes, int n_in,
                              void* d_out, int out_size) {
    const float* x     = (const float*)d_in[0];
    const float* qkvw  = (const float*)d_in[1];
    const float* ow    = (const float*)d_in[2];
    const float* gamma = (const float*)d_in[3];
    const float* beta  = (const float*)d_in[4];
    float* out = (float*)d_out;

    __nv_bfloat16 *xn, *wqkv, *wo, *qkv, *pr, *av;
    float *sc;
    cudaGetSymbolAddress((void**)&xn,   g_xn);
    cudaGetSymbolAddress((void**)&wqkv, g_wqkv);
    cudaGetSymbolAddress((void**)&wo,   g_wo);
    cudaGetSymbolAddress((void**)&qkv,  g_qkv);
    cudaGetSymbolAddress((void**)&sc,   g_sc);
    cudaGetSymbolAddress((void**)&pr,   g_pr);
    cudaGetSymbolAddress((void**)&av,   g_av);

    cudaFuncSetAttribute(gemm_bf16<false, 2, false, false>,
                         cudaFuncAttributeMaxDynamicSharedMemorySize, SMEM_BYTES);
    cudaFuncSetAttribute(gemm_bf16<true,  0, true,  false>,
                         cudaFuncAttributeMaxDynamicSharedMemorySize, SMEM_BYTES);
    cudaFuncSetAttribute(gemm_bf16<false, 2, false, true>,
                         cudaFuncAttributeMaxDynamicSharedMemorySize, SMEM_BYTES);
    cudaFuncSetAttribute(gemm_bf16<false, 1, false, false>,
                         cudaFuncAttributeMaxDynamicSharedMemorySize, SMEM_BYTES);

    const int ROWS = BATCH * SEQ;  // 8192
    const long sQKV = (long)SEQ * NQKV;
    const long sSS  = (long)SEQ * SEQ;
    const long sSH  = (long)SEQ * HID;

    // 1) fused prep: weight converts + LayerNorm (one launch)
    const int n41 = HID * NQKV / 4, n42 = HID * HID / 4;
    const int nCvt = (n41 + n42 + 255) / 256;
    prep_kernel<<<nCvt + ROWS, 256>>>(
        (const float4*)qkvw, (uint32_t*)wqkv, n41,
        (const float4*)ow,   (uint32_t*)wo,   n42,
        nCvt, x, gamma, beta, xn);

    // 2) QKV projection: [8192,2048] @ [2048,6144] -> bf16
    gemm_bf16<false, 2, false, false><<<dim3(NQKV / 128, ROWS / 128, 1), 256, SMEM_BYTES>>>(
        xn, HID, 0, wqkv, NQKV, 0, qkv, NQKV, 0, HID, nullptr, 0);

    // 3) scores = Q @ K^T per batch, packed lower-triangular grid -> fp32
    const int nTri = (SEQ / 128) * (SEQ / 128 + 1) / 2;   // 136
    gemm_bf16<true, 0, true, false><<<dim3(nTri, 1, BATCH), 256, SMEM_BYTES>>>(
        qkv, NQKV, sQKV, qkv + HID, NQKV, sQKV, sc, SEQ, sSS, HID, nullptr, 0);

    // 4) causal softmax, single-pass in registers -> bf16 probs
    softmax_kernel<<<ROWS, 256>>>(sc, pr, 1.0f / sqrtf((float)HID));

    // 5) attn @ V per batch (K clipped at diagonal; heavy blocks first) -> bf16
    gemm_bf16<false, 2, false, true><<<dim3(HID / 128, SEQ / 128, BATCH), 256, SMEM_BYTES>>>(
        pr, SEQ, sSS, qkv + 2 * HID, NQKV, sQKV, av, HID, sSH, SEQ, nullptr, 0);

    // 6) O projection + residual: [8192,2048] @ [2048,2048] + x -> fp32 out
    gemm_bf16<false, 1, false, false><<<dim3(HID / 128, ROWS / 128, 1), 256, SMEM_BYTES>>>(
        av, HID, 0, wo, HID, 0, out, HID, 0, HID, x, HID);
}

// round 11
// speedup vs baseline: 1.0482x; 1.0303x over previous
#include <cuda_runtime.h>
#include <cuda_bf16.h>
#include <cstdint>
#include <math.h>

#define HID  2048
#define SEQ  2048
#define BATCH 4
#define NQKV 6144   // 3*HID

#define STAGES 3
#define BK 64
#define SSTRIDE 9216          // bf16 elems per operand per stage (128*72)
#define SMEM_BYTES (2 * STAGES * SSTRIDE * 2)   // 110592
#define GTHREADS 128          // 4 warps per CTA, warp tile 64x64

// ---------------- scratch (device globals; no allocations allowed) ----------
__device__ __align__(16) __nv_bfloat16 g_xn  [BATCH * SEQ * HID];    // 32 MB
__device__ __align__(16) __nv_bfloat16 g_wqkv[HID * NQKV];           // 24 MB
__device__ __align__(16) __nv_bfloat16 g_wo  [HID * HID];            //  8 MB
__device__ __align__(16) __nv_bfloat16 g_qkv [BATCH * SEQ * NQKV];   // 96 MB
__device__ __align__(16) float         g_sc  [BATCH * SEQ * SEQ];    // 64 MB
__device__ __align__(16) __nv_bfloat16 g_pr  [BATCH * SEQ * SEQ];    // 32 MB
__device__ __align__(16) __nv_bfloat16 g_av  [BATCH * SEQ * HID];    // 32 MB

// ---------------- helpers ----------------------------------------------------
__device__ __forceinline__ void cpa16(uint32_t dst, const void* src) {
    asm volatile("cp.async.cg.shared.global [%0], [%1], 16;" :: "r"(dst), "l"(src));
}
__device__ __forceinline__ void cpa_commit() {
    asm volatile("cp.async.commit_group;");
}
template <int N>
__device__ __forceinline__ void cpa_wait() {
    asm volatile("cp.async.wait_group %0;" :: "n"(N));
}

// ---------------- fused prep: weight converts + LayerNorm --------------------
__global__ void prep_kernel(const float4* __restrict__ w1, uint32_t* __restrict__ o1, int n41,
                            const float4* __restrict__ w2, uint32_t* __restrict__ o2, int n42,
                            int nCvt,
                            const float* __restrict__ x,
                            const float* __restrict__ gamma,
                            const float* __restrict__ beta,
                            __nv_bfloat16* __restrict__ xn) {
    if (blockIdx.x < (unsigned)nCvt) {
        int i = blockIdx.x * blockDim.x + threadIdx.x;
        const float4* in; uint32_t* out;
        if (i < n41) { in = w1; out = o1; }
        else if (i < n41 + n42) { in = w2 - n41; out = o2 - (size_t)n41 * 2; }
        else return;
        float4 v = in[i];
        __nv_bfloat162 a = __float22bfloat162_rn(make_float2(v.x, v.y));
        __nv_bfloat162 b = __float22bfloat162_rn(make_float2(v.z, v.w));
        out[(size_t)i * 2 + 0] = *reinterpret_cast<uint32_t*>(&a);
        out[(size_t)i * 2 + 1] = *reinterpret_cast<uint32_t*>(&b);
        return;
    }

    const int row = blockIdx.x - nCvt;
    const float* xr = x + (size_t)row * HID;
    __nv_bfloat16* orow = xn + (size_t)row * HID;
    const int tid = threadIdx.x;

    float v[8];
    float s = 0.f, s2 = 0.f;
#pragma unroll
    for (int i = 0; i < 8; i++) {
        float val = xr[tid + i * 256];
        v[i] = val; s += val; s2 += val * val;
    }
    __shared__ float red[2][8];
#pragma unroll
    for (int o = 16; o > 0; o >>= 1) {
        s  += __shfl_down_sync(0xffffffffu, s,  o);
        s2 += __shfl_down_sync(0xffffffffu, s2, o);
    }
    const int w = tid >> 5, l = tid & 31;
    if (l == 0) { red[0][w] = s; red[1][w] = s2; }
    __syncthreads();
    if (w == 0) {
        float a  = red[0][l & 7];
        float b2 = red[1][l & 7];
#pragma unroll
        for (int o = 4; o > 0; o >>= 1) {
            a  += __shfl_down_sync(0xffffffffu, a,  o);
            b2 += __shfl_down_sync(0xffffffffu, b2, o);
        }
        if (l == 0) { red[0][0] = a; red[1][0] = b2; }
    }
    __syncthreads();
    const float mean = red[0][0] * (1.f / HID);
    const float var  = red[1][0] * (1.f / HID) - mean * mean;
    const float rstd = rsqrtf(var + 1e-5f);
#pragma unroll
    for (int i = 0; i < 8; i++) {
        int h = tid + i * 256;
        orow[h] = __float2bfloat16((v[i] - mean) * rstd * gamma[h] + beta[h]);
    }
}

// ---------------- causal softmax: single-pass, row in registers --------------
__global__ void softmax_kernel(const float* __restrict__ sc,
                               __nv_bfloat16* __restrict__ pr, float scale) {
    const int row = blockIdx.x;            // b*SEQ + q
    const int q = row & (SEQ - 1);
    const float* p = sc + (size_t)row * SEQ;
    __nv_bfloat16* po = pr + (size_t)row * SEQ;
    const int n = q + 1;
    const int nend = ((q >> 7) + 1) << 7;  // PV reads only [0, nend)
    const int tid = threadIdx.x;
    __shared__ float red[8];

    float v[8];
    float mx = -1e30f;
    int cnt = 0;
#pragma unroll
    for (int i = 0; i < 8; i++) {
        int t = tid + i * 256;
        if (t < n) {
            float val = p[t] * scale;
            v[i] = val;
            mx = fmaxf(mx, val);
            cnt = i + 1;
        }
    }
#pragma unroll
    for (int o = 16; o > 0; o >>= 1) mx = fmaxf(mx, __shfl_down_sync(0xffffffffu, mx, o));
    if ((tid & 31) == 0) red[tid >> 5] = mx;
    __syncthreads();
    if (tid < 32) {
        float a = red[tid & 7];
#pragma unroll
        for (int o = 4; o > 0; o >>= 1) a = fmaxf(a, __shfl_down_sync(0xffffffffu, a, o));
        if (tid == 0) red[0] = a;
    }
    __syncthreads();
    mx = red[0];
    __syncthreads();

    float sum = 0.f;
#pragma unroll
    for (int i = 0; i < 8; i++) {
        if (i < cnt) {
            float e = __expf(v[i] - mx);
            v[i] = e;
            sum += e;
        }
    }
#pragma unroll
    for (int o = 16; o > 0; o >>= 1) sum += __shfl_down_sync(0xffffffffu, sum, o);
    if ((tid & 31) == 0) red[tid >> 5] = sum;
    __syncthreads();
    if (tid < 32) {
        float a = red[tid & 7];
#pragma unroll
        for (int o = 4; o > 0; o >>= 1) a += __shfl_down_sync(0xffffffffu, a, o);
        if (tid == 0) red[0] = a;
    }
    __syncthreads();
    const float inv = 1.f / red[0];
#pragma unroll
    for (int i = 0; i < 8; i++) {
        int t = tid + i * 256;
        if (i < cnt) po[t] = __float2bfloat16(v[i] * inv);
        else if (t < nend) po[t] = __float2bfloat16(0.f);
    }
}

// ---------------- bf16 tensor-core GEMM (3-stage, BK=64, 4 warps 64x64) ------
// C[M,N] = A[M,K] @ B. A row-major bf16 (lda).
// BKMAJ=true:  B stored [N,K] k-contig (ldb) -> A @ B^T.
// BKMAJ=false: B stored [K,N] n-contig (ldb).
// EPI: 0 = fp32 out, 1 = fp32 out + residual R, 2 = bf16 out.
// TRIPACK: grid.x is a packed lower-triangular (mb,nb) index.
// CKLIM: clip K at diagonal; mb order reversed (heavy blocks first).
// Block 128x128x64, 4 warps of 64x64 (1 warp/SMSP/CTA), 2 CTAs/SM.
template <bool BKMAJ, int EPI, bool TRIPACK, bool CKLIM>
__global__ void __launch_bounds__(GTHREADS, 2)
gemm_bf16(const __nv_bfloat16* __restrict__ A, int lda, long sA,
          const __nv_bfloat16* __restrict__ B, int ldb, long sB,
          void* __restrict__ Cv, int ldc, long sC,
          int Kdim,
          const float* __restrict__ R, int ldr) {
    int mb, nb;
    if (TRIPACK) {
        const int t = blockIdx.x;
        int m = (int)((sqrtf(8.f * t + 1.f) - 1.f) * 0.5f);
        while ((m + 1) * (m + 2) / 2 <= t) m++;
        while (m * (m + 1) / 2 > t) m--;
        mb = m;
        nb = t - m * (m + 1) / 2;
    } else {
        mb = CKLIM ? (gridDim.y - 1 - blockIdx.y) : blockIdx.y;
        nb = blockIdx.x;
    }

    A += (long)blockIdx.z * sA;
    B += (long)blockIdx.z * sB;

    const int kend = CKLIM ? min(Kdim, (mb + 1) * 128) : Kdim;
    const int nK = kend >> 6;   // BK = 64

    extern __shared__ __align__(16) __nv_bfloat16 sm[];
    const uint32_t smBase = (uint32_t)__cvta_generic_to_shared(sm);
    const uint32_t aBase = smBase;
    const uint32_t bBase = smBase + STAGES * SSTRIDE * 2;

    const int tid = threadIdx.x;
    const int warp = tid >> 5, lane = tid & 31;
    const int gid = lane >> 2, tig = lane & 3;
    const int wm = (warp & 1) * 64, wn = (warp >> 1) * 64;
    const int bm0 = mb * 128, bn0 = nb * 128;

    float c[4][8][4];
#pragma unroll
    for (int i = 0; i < 4; i++)
#pragma unroll
        for (int j = 0; j < 8; j++)
#pragma unroll
            for (int k = 0; k < 4; k++) c[i][j][k] = 0.f;

    // ldmatrix per-lane coordinates
    const int arow = (lane & 7) + ((lane >> 3) & 1) * 8;
    const int acol = ((lane >> 4) & 1) * 8;
    const int ln8 = lane & 7, sel = lane >> 3;
    const int bt_row = ((sel >> 1) & 1) * 8 + ln8;   // BKMAJ=true: n within 16
    const int bt_col = (sel & 1) * 8;                // k-half
    const int bf_row = (sel & 1) * 8 + ln8;          // BKMAJ=false: k within 16
    const int bf_col = ((sel >> 1) & 1) * 8;         // n within 16

    auto fillA = [&](int st, int k0) {
#pragma unroll
        for (int p = 0; p < 8; p++) {
            int fid = tid + p * GTHREADS;
            int r = fid >> 3, kq = fid & 7;
            cpa16(aBase + (st * SSTRIDE + r * 72 + kq * 8) * 2,
                  A + (size_t)(bm0 + r) * lda + k0 + kq * 8);
        }
    };
    auto fillB = [&](int st, int k0) {
#pragma unroll
        for (int p = 0; p < 8; p++) {
            int fid = tid + p * GTHREADS;
            if (BKMAJ) {
                int r = fid >> 3, kq = fid & 7;
                cpa16(bBase + (st * SSTRIDE + r * 72 + kq * 8) * 2,
                      B + (size_t)(bn0 + r) * ldb + k0 + kq * 8);
            } else {
                int kr = fid >> 4, nq = fid & 15;
                cpa16(bBase + (st * SSTRIDE + kr * 136 + nq * 8) * 2,
                      B + (size_t)(k0 + kr) * ldb + bn0 + nq * 8);
            }
        }
    };

    // prologue: fill stages 0..1
#pragma unroll
    for (int st = 0; st < STAGES - 1; st++) {
        fillA(st, st * BK); fillB(st, st * BK);
        cpa_commit();
    }

    int buf = 0, fb = STAGES - 1;
    for (int kt = 0; kt < nK; kt++) {
        cpa_wait<STAGES - 2>();
        __syncthreads();

        // EARLY fill: start stage kt+2's copies before this iter's MMA work.
        const int kf = kt + STAGES - 1;
        if (kf < nK) { fillA(fb, kf * BK); fillB(fb, kf * BK); }
        cpa_commit();

        const uint32_t aS = aBase + buf * SSTRIDE * 2;
        const uint32_t bS = bBase + buf * SSTRIDE * 2;

#pragma unroll
        for (int kc = 0; kc < 4; kc++) {
            const int kk = kc * 16;
            uint32_t af[4][4], bfr[4][4];
#pragma unroll
            for (int mf = 0; mf < 4; mf++) {
                uint32_t a = aS + ((wm + mf * 16 + arow) * 72 + acol + kk) * 2;
                asm volatile("ldmatrix.sync.aligned.m8n8.x4.shared.b16 {%0,%1,%2,%3},[%4];"
                    : "=r"(af[mf][0]), "=r"(af[mf][1]), "=r"(af[mf][2]), "=r"(af[mf][3])
                    : "r"(a));
            }
#pragma unroll
            for (int nfp = 0; nfp < 4; nfp++) {
                if (BKMAJ) {
                    uint32_t a = bS + ((wn + nfp * 16 + bt_row) * 72 + kk + bt_col) * 2;
                    asm volatile("ldmatrix.sync.aligned.m8n8.x4.shared.b16 {%0,%1,%2,%3},[%4];"
                        : "=r"(bfr[nfp][0]), "=r"(bfr[nfp][1]),
                          "=r"(bfr[nfp][2]), "=r"(bfr[nfp][3])
                        : "r"(a));
                } else {
                    uint32_t a = bS + ((kk + bf_row) * 136 + wn + nfp * 16 + bf_col) * 2;
                    asm volatile("ldmatrix.sync.aligned.m8n8.x4.trans.shared.b16 {%0,%1,%2,%3},[%4];"
                        : "=r"(bfr[nfp][0]), "=r"(bfr[nfp][1]),
                          "=r"(bfr[nfp][2]), "=r"(bfr[nfp][3])
                        : "r"(a));
                }
            }
#pragma unroll
            for (int mf = 0; mf < 4; mf++)
#pragma unroll
                for (int nf = 0; nf < 8; nf++) {
                    asm volatile(
                        "mma.sync.aligned.m16n8k16.row.col.f32.bf16.bf16.f32 "
                        "{%0,%1,%2,%3},{%4,%5,%6,%7},{%8,%9},{%0,%1,%2,%3};"
                        : "+f"(c[mf][nf][0]), "+f"(c[mf][nf][1]),
                          "+f"(c[mf][nf][2]), "+f"(c[mf][nf][3])
                        : "r"(af[mf][0]), "r"(af[mf][1]), "r"(af[mf][2]), "r"(af[mf][3]),
                          "r"(bfr[nf >> 1][(nf & 1) * 2]), "r"(bfr[nf >> 1][(nf & 1) * 2 + 1]));
                }
        }

        buf = (buf + 1 == STAGES) ? 0 : buf + 1;
        fb  = (fb  + 1 == STAGES) ? 0 : fb  + 1;
    }

    // epilogue
    if (EPI == 2) {
        __nv_bfloat16* C = (__nv_bfloat16*)Cv + (long)blockIdx.z * sC;
#pragma unroll
        for (int mf = 0; mf < 4; mf++) {
            const int r0 = bm0 + wm + mf * 16 + gid;
#pragma unroll
            for (int nf = 0; nf < 8; nf++) {
                const int cc = bn0 + wn + nf * 8 + tig * 2;
                __nv_bfloat162 v0 = __float22bfloat162_rn(make_float2(c[mf][nf][0], c[mf][nf][1]));
                __nv_bfloat162 v1 = __float22bfloat162_rn(make_float2(c[mf][nf][2], c[mf][nf][3]));
                *reinterpret_cast<__nv_bfloat162*>(C + (size_t)r0 * ldc + cc) = v0;
                *reinterpret_cast<__nv_bfloat162*>(C + (size_t)(r0 + 8) * ldc + cc) = v1;
            }
        }
    } else {
        float* C = (float*)Cv + (long)blockIdx.z * sC;
#pragma unroll
        for (int mf = 0; mf < 4; mf++) {
            const int r0 = bm0 + wm + mf * 16 + gid;
#pragma unroll
            for (int nf = 0; nf < 8; nf++) {
                const int cc = bn0 + wn + nf * 8 + tig * 2;
                float2 v0 = make_float2(c[mf][nf][0], c[mf][nf][1]);
                float2 v1 = make_float2(c[mf][nf][2], c[mf][nf][3]);
                if (EPI == 1) {
                    const float2 q0 = *reinterpret_cast<const float2*>(R + (size_t)r0 * ldr + cc);
                    const float2 q1 = *reinterpret_cast<const float2*>(R + (size_t)(r0 + 8) * ldr + cc);
                    v0.x += q0.x; v0.y += q0.y;
                    v1.x += q1.x; v1.y += q1.y;
                }
                *reinterpret_cast<float2*>(C + (size_t)r0 * ldc + cc) = v0;
                *reinterpret_cast<float2*>(C + (size_t)(r0 + 8) * ldc + cc) = v1;
            }
        }
    }
}

// ---------------- launch ------------------------------------------------------
extern "C" void kernel_launch(void* const* d_in, const int* in_sizes, int n_in,
                              void* d_out, int out_size) {
    const float* x     = (const float*)d_in[0];
    const float* qkvw  = (const float*)d_in[1];
    const float* ow    = (const float*)d_in[2];
    const float* gamma = (const float*)d_in[3];
    const float* beta  = (const float*)d_in[4];
    float* out = (float*)d_out;

    __nv_bfloat16 *xn, *wqkv, *wo, *qkv, *pr, *av;
    float *sc;
    cudaGetSymbolAddress((void**)&xn,   g_xn);
    cudaGetSymbolAddress((void**)&wqkv, g_wqkv);
    cudaGetSymbolAddress((void**)&wo,   g_wo);
    cudaGetSymbolAddress((void**)&qkv,  g_qkv);
    cudaGetSymbolAddress((void**)&sc,   g_sc);
    cudaGetSymbolAddress((void**)&pr,   g_pr);
    cudaGetSymbolAddress((void**)&av,   g_av);

    cudaFuncSetAttribute(gemm_bf16<false, 2, false, false>,
                         cudaFuncAttributeMaxDynamicSharedMemorySize, SMEM_BYTES);
    cudaFuncSetAttribute(gemm_bf16<true,  0, true,  false>,
                         cudaFuncAttributeMaxDynamicSharedMemorySize, SMEM_BYTES);
    cudaFuncSetAttribute(gemm_bf16<false, 2, false, true>,
                         cudaFuncAttributeMaxDynamicSharedMemorySize, SMEM_BYTES);
    cudaFuncSetAttribute(gemm_bf16<false, 1, false, false>,
                         cudaFuncAttributeMaxDynamicSharedMemorySize, SMEM_BYTES);

    const int ROWS = BATCH * SEQ;  // 8192
    const long sQKV = (long)SEQ * NQKV;
    const long sSS  = (long)SEQ * SEQ;
    const long sSH  = (long)SEQ * HID;

    // 1) fused prep: weight converts + LayerNorm (one launch)
    const int n41 = HID * NQKV / 4, n42 = HID * HID / 4;
    const int nCvt = (n41 + n42 + 255) / 256;
    prep_kernel<<<nCvt + ROWS, 256>>>(
        (const float4*)qkvw, (uint32_t*)wqkv, n41,
        (const float4*)ow,   (uint32_t*)wo,   n42,
        nCvt, x, gamma, beta, xn);

    // 2) QKV projection: [8192,2048] @ [2048,6144] -> bf16
    gemm_bf16<false, 2, false, false><<<dim3(NQKV / 128, ROWS / 128, 1), GTHREADS, SMEM_BYTES>>>(
        xn, HID, 0, wqkv, NQKV, 0, qkv, NQKV, 0, HID, nullptr, 0);

    // 3) scores = Q @ K^T per batch, packed lower-triangular grid -> fp32
    const int nTri = (SEQ / 128) * (SEQ / 128 + 1) / 2;   // 136
    gemm_bf16<true, 0, true, false><<<dim3(nTri, 1, BATCH), GTHREADS, SMEM_BYTES>>>(
        qkv, NQKV, sQKV, qkv + HID, NQKV, sQKV, sc, SEQ, sSS, HID, nullptr, 0);

    // 4) causal softmax, single-pass in registers -> bf16 probs
    softmax_kernel<<<ROWS, 256>>>(sc, pr, 1.0f / sqrtf((float)HID));

    // 5) attn @ V per batch (K clipped at diagonal; heavy blocks first) -> bf16
    gemm_bf16<false, 2, false, true><<<dim3(HID / 128, SEQ / 128, BATCH), GTHREADS, SMEM_BYTES>>>(
        pr, SEQ, sSS, qkv + 2 * HID, NQKV, sQKV, av, HID, sSH, SEQ, nullptr, 0);

    // 6) O projection + residual: [8192,2048] @ [2048,2048] + x -> fp32 out
    gemm_bf16<false, 1, false, false><<<dim3(HID / 128, ROWS / 128, 1), GTHREADS, SMEM_BYTES>>>(
        av, HID, 0, wo, HID, 0, out, HID, 0, HID, x, HID);
}

// round 12
// speedup vs baseline: 1.0504x; 1.0021x over previous
#include <cuda_runtime.h>
#include <cuda_bf16.h>
#include <cstdint>
#include <math.h>

#define HID  2048
#define SEQ  2048
#define BATCH 4
#define NQKV 6144   // 3*HID

#define STAGES 3
#define BK 64
#define SSTRIDE 9216          // bf16 elems per operand per stage (128*72)
#define SMEM_BYTES (2 * STAGES * SSTRIDE * 2)   // 110592
#define GTHREADS 128          // 4 warps per CTA, warp tile 64x64

// ---------------- scratch (device globals; no allocations allowed) ----------
__device__ __align__(16) __nv_bfloat16 g_xn  [BATCH * SEQ * HID];    // 32 MB
__device__ __align__(16) __nv_bfloat16 g_wqkv[HID * NQKV];           // 24 MB
__device__ __align__(16) __nv_bfloat16 g_wo  [HID * HID];            //  8 MB
__device__ __align__(16) __nv_bfloat16 g_qkv [BATCH * SEQ * NQKV];   // 96 MB
__device__ __align__(16) float         g_sc  [BATCH * SEQ * SEQ];    // 64 MB
__device__ __align__(16) __nv_bfloat16 g_pr  [BATCH * SEQ * SEQ];    // 32 MB
__device__ __align__(16) __nv_bfloat16 g_av  [BATCH * SEQ * HID];    // 32 MB

// ---------------- helpers ----------------------------------------------------
__device__ __forceinline__ void cpa16(uint32_t dst, const void* src) {
    asm volatile("cp.async.cg.shared.global [%0], [%1], 16;" :: "r"(dst), "l"(src));
}
__device__ __forceinline__ void cpa_commit() {
    asm volatile("cp.async.commit_group;");
}
template <int N>
__device__ __forceinline__ void cpa_wait() {
    asm volatile("cp.async.wait_group %0;" :: "n"(N));
}
// PDL: block until the primary (previous) kernel's memory is visible.
__device__ __forceinline__ void gdc_wait() {
    asm volatile("griddepcontrol.wait;" ::: "memory");
}
// PDL: allow the dependent (next) kernel to begin scheduling.
__device__ __forceinline__ void gdc_launch() {
    asm volatile("griddepcontrol.launch_dependents;" ::: "memory");
}

// ---------------- fused prep: weight converts + LayerNorm --------------------
__global__ void prep_kernel(const float4* __restrict__ w1, uint32_t* __restrict__ o1, int n41,
                            const float4* __restrict__ w2, uint32_t* __restrict__ o2, int n42,
                            int nCvt,
                            const float* __restrict__ x,
                            const float* __restrict__ gamma,
                            const float* __restrict__ beta,
                            __nv_bfloat16* __restrict__ xn) {
    if (blockIdx.x < (unsigned)nCvt) {
        int i = blockIdx.x * blockDim.x + threadIdx.x;
        const float4* in; uint32_t* out;
        if (i < n41) { in = w1; out = o1; }
        else if (i < n41 + n42) { in = w2 - n41; out = o2 - (size_t)n41 * 2; }
        else return;
        float4 v = in[i];
        __nv_bfloat162 a = __float22bfloat162_rn(make_float2(v.x, v.y));
        __nv_bfloat162 b = __float22bfloat162_rn(make_float2(v.z, v.w));
        out[(size_t)i * 2 + 0] = *reinterpret_cast<uint32_t*>(&a);
        out[(size_t)i * 2 + 1] = *reinterpret_cast<uint32_t*>(&b);
        return;
    }

    const int row = blockIdx.x - nCvt;
    const float* xr = x + (size_t)row * HID;
    __nv_bfloat16* orow = xn + (size_t)row * HID;
    const int tid = threadIdx.x;

    float v[8];
    float s = 0.f, s2 = 0.f;
#pragma unroll
    for (int i = 0; i < 8; i++) {
        float val = xr[tid + i * 256];
        v[i] = val; s += val; s2 += val * val;
    }
    __shared__ float red[2][8];
#pragma unroll
    for (int o = 16; o > 0; o >>= 1) {
        s  += __shfl_down_sync(0xffffffffu, s,  o);
        s2 += __shfl_down_sync(0xffffffffu, s2, o);
    }
    const int w = tid >> 5, l = tid & 31;
    if (l == 0) { red[0][w] = s; red[1][w] = s2; }
    __syncthreads();
    if (w == 0) {
        float a  = red[0][l & 7];
        float b2 = red[1][l & 7];
#pragma unroll
        for (int o = 4; o > 0; o >>= 1) {
            a  += __shfl_down_sync(0xffffffffu, a,  o);
            b2 += __shfl_down_sync(0xffffffffu, b2, o);
        }
        if (l == 0) { red[0][0] = a; red[1][0] = b2; }
    }
    __syncthreads();
    const float mean = red[0][0] * (1.f / HID);
    const float var  = red[1][0] * (1.f / HID) - mean * mean;
    const float rstd = rsqrtf(var + 1e-5f);
#pragma unroll
    for (int i = 0; i < 8; i++) {
        int h = tid + i * 256;
        orow[h] = __float2bfloat16((v[i] - mean) * rstd * gamma[h] + beta[h]);
    }
}

// ---------------- causal softmax: single-pass, row in registers --------------
__global__ void softmax_kernel(const float* __restrict__ sc,
                               __nv_bfloat16* __restrict__ pr, float scale) {
    const int row = blockIdx.x;            // b*SEQ + q
    const int q = row & (SEQ - 1);
    const float* p = sc + (size_t)row * SEQ;
    __nv_bfloat16* po = pr + (size_t)row * SEQ;
    const int n = q + 1;
    const int nend = ((q >> 7) + 1) << 7;  // PV reads only [0, nend)
    const int tid = threadIdx.x;
    __shared__ float red[8];

    gdc_wait();   // scores from QKT must be visible

    float v[8];
    float mx = -1e30f;
    int cnt = 0;
#pragma unroll
    for (int i = 0; i < 8; i++) {
        int t = tid + i * 256;
        if (t < n) {
            float val = p[t] * scale;
            v[i] = val;
            mx = fmaxf(mx, val);
            cnt = i + 1;
        }
    }
#pragma unroll
    for (int o = 16; o > 0; o >>= 1) mx = fmaxf(mx, __shfl_down_sync(0xffffffffu, mx, o));
    if ((tid & 31) == 0) red[tid >> 5] = mx;
    __syncthreads();
    if (tid < 32) {
        float a = red[tid & 7];
#pragma unroll
        for (int o = 4; o > 0; o >>= 1) a = fmaxf(a, __shfl_down_sync(0xffffffffu, a, o));
        if (tid == 0) red[0] = a;
    }
    __syncthreads();
    mx = red[0];
    __syncthreads();

    float sum = 0.f;
#pragma unroll
    for (int i = 0; i < 8; i++) {
        if (i < cnt) {
            float e = __expf(v[i] - mx);
            v[i] = e;
            sum += e;
        }
    }
#pragma unroll
    for (int o = 16; o > 0; o >>= 1) sum += __shfl_down_sync(0xffffffffu, sum, o);
    if ((tid & 31) == 0) red[tid >> 5] = sum;
    __syncthreads();
    if (tid < 32) {
        float a = red[tid & 7];
#pragma unroll
        for (int o = 4; o > 0; o >>= 1) a += __shfl_down_sync(0xffffffffu, a, o);
        if (tid == 0) red[0] = a;
    }
    __syncthreads();
    gdc_launch();   // let PV start scheduling (it still waits for our stores)
    const float inv = 1.f / red[0];
#pragma unroll
    for (int i = 0; i < 8; i++) {
        int t = tid + i * 256;
        if (i < cnt) po[t] = __float2bfloat16(v[i] * inv);
        else if (t < nend) po[t] = __float2bfloat16(0.f);
    }
}

// ---------------- bf16 tensor-core GEMM (3-stage, BK=64, 4 warps 64x64) ------
// C[M,N] = A[M,K] @ B. A row-major bf16 (lda).
// BKMAJ=true:  B stored [N,K] k-contig (ldb) -> A @ B^T.
// BKMAJ=false: B stored [K,N] n-contig (ldb).
// EPI: 0 = fp32 out, 1 = fp32 out + residual R, 2 = bf16 out.
// TRIPACK: grid.x is a packed lower-triangular (mb,nb) index.
// CKLIM: clip K at diagonal; mb order reversed (heavy blocks first).
// PREB: B operand is NOT produced by the primary kernel -> prefill before wait.
// Block 128x128x64, 4 warps of 64x64 (1 warp/SMSP/CTA), 2 CTAs/SM.
template <bool BKMAJ, int EPI, bool TRIPACK, bool CKLIM, bool PREB>
__global__ void __launch_bounds__(GTHREADS, 2)
gemm_bf16(const __nv_bfloat16* __restrict__ A, int lda, long sA,
          const __nv_bfloat16* __restrict__ B, int ldb, long sB,
          void* __restrict__ Cv, int ldc, long sC,
          int Kdim,
          const float* __restrict__ R, int ldr) {
    int mb, nb;
    if (TRIPACK) {
        const int t = blockIdx.x;
        int m = (int)((sqrtf(8.f * t + 1.f) - 1.f) * 0.5f);
        while ((m + 1) * (m + 2) / 2 <= t) m++;
        while (m * (m + 1) / 2 > t) m--;
        mb = m;
        nb = t - m * (m + 1) / 2;
    } else {
        mb = CKLIM ? (gridDim.y - 1 - blockIdx.y) : blockIdx.y;
        nb = blockIdx.x;
    }

    A += (long)blockIdx.z * sA;
    B += (long)blockIdx.z * sB;

    const int kend = CKLIM ? min(Kdim, (mb + 1) * 128) : Kdim;
    const int nK = kend >> 6;   // BK = 64; >= 2 for all our shapes

    extern __shared__ __align__(16) __nv_bfloat16 sm[];
    const uint32_t smBase = (uint32_t)__cvta_generic_to_shared(sm);
    const uint32_t aBase = smBase;
    const uint32_t bBase = smBase + STAGES * SSTRIDE * 2;

    const int tid = threadIdx.x;
    const int warp = tid >> 5, lane = tid & 31;
    const int gid = lane >> 2, tig = lane & 3;
    const int wm = (warp & 1) * 64, wn = (warp >> 1) * 64;
    const int bm0 = mb * 128, bn0 = nb * 128;

    float c[4][8][4];
#pragma unroll
    for (int i = 0; i < 4; i++)
#pragma unroll
        for (int j = 0; j < 8; j++)
#pragma unroll
            for (int k = 0; k < 4; k++) c[i][j][k] = 0.f;

    // ldmatrix per-lane coordinates
    const int arow = (lane & 7) + ((lane >> 3) & 1) * 8;
    const int acol = ((lane >> 4) & 1) * 8;
    const int ln8 = lane & 7, sel = lane >> 3;
    const int bt_row = ((sel >> 1) & 1) * 8 + ln8;   // BKMAJ=true: n within 16
    const int bt_col = (sel & 1) * 8;                // k-half
    const int bf_row = (sel & 1) * 8 + ln8;          // BKMAJ=false: k within 16
    const int bf_col = ((sel >> 1) & 1) * 8;         // n within 16

    auto fillA = [&](int st, int k0) {
#pragma unroll
        for (int p = 0; p < 8; p++) {
            int fid = tid + p * GTHREADS;
            int r = fid >> 3, kq = fid & 7;
            cpa16(aBase + (st * SSTRIDE + r * 72 + kq * 8) * 2,
                  A + (size_t)(bm0 + r) * lda + k0 + kq * 8);
        }
    };
    auto fillB = [&](int st, int k0) {
#pragma unroll
        for (int p = 0; p < 8; p++) {
            int fid = tid + p * GTHREADS;
            if (BKMAJ) {
                int r = fid >> 3, kq = fid & 7;
                cpa16(bBase + (st * SSTRIDE + r * 72 + kq * 8) * 2,
                      B + (size_t)(bn0 + r) * ldb + k0 + kq * 8);
            } else {
                int kr = fid >> 4, nq = fid & 15;
                cpa16(bBase + (st * SSTRIDE + kr * 136 + nq * 8) * 2,
                      B + (size_t)(k0 + kr) * ldb + bn0 + nq * 8);
            }
        }
    };

    // prologue with PDL: B that doesn't come from the primary fills pre-wait.
    if (PREB) { fillB(0, 0); fillB(1, BK); }
    gdc_wait();
    fillA(0, 0); if (!PREB) fillB(0, 0);
    cpa_commit();
    fillA(1, BK); if (!PREB) fillB(1, BK);
    cpa_commit();
    // groups: PREB ? {B0,B1,A0},{A1} : {A0,B0},{A1,B1} — wait<1> semantics hold.

    int buf = 0, fb = STAGES - 1;
    for (int kt = 0; kt < nK; kt++) {
        cpa_wait<STAGES - 2>();
        __syncthreads();

        // EARLY fill: start stage kt+2's copies before this iter's MMA work.
        const int kf = kt + STAGES - 1;
        if (kf < nK) { fillA(fb, kf * BK); fillB(fb, kf * BK); }
        cpa_commit();

        const uint32_t aS = aBase + buf * SSTRIDE * 2;
        const uint32_t bS = bBase + buf * SSTRIDE * 2;

#pragma unroll
        for (int kc = 0; kc < 4; kc++) {
            const int kk = kc * 16;
            uint32_t af[4][4], bfr[4][4];
#pragma unroll
            for (int mf = 0; mf < 4; mf++) {
                uint32_t a = aS + ((wm + mf * 16 + arow) * 72 + acol + kk) * 2;
                asm volatile("ldmatrix.sync.aligned.m8n8.x4.shared.b16 {%0,%1,%2,%3},[%4];"
                    : "=r"(af[mf][0]), "=r"(af[mf][1]), "=r"(af[mf][2]), "=r"(af[mf][3])
                    : "r"(a));
            }
#pragma unroll
            for (int nfp = 0; nfp < 4; nfp++) {
                if (BKMAJ) {
                    uint32_t a = bS + ((wn + nfp * 16 + bt_row) * 72 + kk + bt_col) * 2;
                    asm volatile("ldmatrix.sync.aligned.m8n8.x4.shared.b16 {%0,%1,%2,%3},[%4];"
                        : "=r"(bfr[nfp][0]), "=r"(bfr[nfp][1]),
                          "=r"(bfr[nfp][2]), "=r"(bfr[nfp][3])
                        : "r"(a));
                } else {
                    uint32_t a = bS + ((kk + bf_row) * 136 + wn + nfp * 16 + bf_col) * 2;
                    asm volatile("ldmatrix.sync.aligned.m8n8.x4.trans.shared.b16 {%0,%1,%2,%3},[%4];"
                        : "=r"(bfr[nfp][0]), "=r"(bfr[nfp][1]),
                          "=r"(bfr[nfp][2]), "=r"(bfr[nfp][3])
                        : "r"(a));
                }
            }
#pragma unroll
            for (int mf = 0; mf < 4; mf++)
#pragma unroll
                for (int nf = 0; nf < 8; nf++) {
                    asm volatile(
                        "mma.sync.aligned.m16n8k16.row.col.f32.bf16.bf16.f32 "
                        "{%0,%1,%2,%3},{%4,%5,%6,%7},{%8,%9},{%0,%1,%2,%3};"
                        : "+f"(c[mf][nf][0]), "+f"(c[mf][nf][1]),
                          "+f"(c[mf][nf][2]), "+f"(c[mf][nf][3])
                        : "r"(af[mf][0]), "r"(af[mf][1]), "r"(af[mf][2]), "r"(af[mf][3]),
                          "r"(bfr[nf >> 1][(nf & 1) * 2]), "r"(bfr[nf >> 1][(nf & 1) * 2 + 1]));
                }
        }

        buf = (buf + 1 == STAGES) ? 0 : buf + 1;
        fb  = (fb  + 1 == STAGES) ? 0 : fb  + 1;
    }

    gdc_launch();   // mainloop done: let the dependent kernel start scheduling

    // epilogue
    if (EPI == 2) {
        __nv_bfloat16* C = (__nv_bfloat16*)Cv + (long)blockIdx.z * sC;
#pragma unroll
        for (int mf = 0; mf < 4; mf++) {
            const int r0 = bm0 + wm + mf * 16 + gid;
#pragma unroll
            for (int nf = 0; nf < 8; nf++) {
                const int cc = bn0 + wn + nf * 8 + tig * 2;
                __nv_bfloat162 v0 = __float22bfloat162_rn(make_float2(c[mf][nf][0], c[mf][nf][1]));
                __nv_bfloat162 v1 = __float22bfloat162_rn(make_float2(c[mf][nf][2], c[mf][nf][3]));
                *reinterpret_cast<__nv_bfloat162*>(C + (size_t)r0 * ldc + cc) = v0;
                *reinterpret_cast<__nv_bfloat162*>(C + (size_t)(r0 + 8) * ldc + cc) = v1;
            }
        }
    } else {
        float* C = (float*)Cv + (long)blockIdx.z * sC;
#pragma unroll
        for (int mf = 0; mf < 4; mf++) {
            const int r0 = bm0 + wm + mf * 16 + gid;
#pragma unroll
            for (int nf = 0; nf < 8; nf++) {
                const int cc = bn0 + wn + nf * 8 + tig * 2;
                float2 v0 = make_float2(c[mf][nf][0], c[mf][nf][1]);
                float2 v1 = make_float2(c[mf][nf][2], c[mf][nf][3]);
                if (EPI == 1) {
                    const float2 q0 = *reinterpret_cast<const float2*>(R + (size_t)r0 * ldr + cc);
                    const float2 q1 = *reinterpret_cast<const float2*>(R + (size_t)(r0 + 8) * ldr + cc);
                    v0.x += q0.x; v0.y += q0.y;
                    v1.x += q1.x; v1.y += q1.y;
                }
                *reinterpret_cast<float2*>(C + (size_t)r0 * ldc + cc) = v0;
                *reinterpret_cast<float2*>(C + (size_t)(r0 + 8) * ldc + cc) = v1;
            }
        }
    }
}

// ---------------- launch ------------------------------------------------------
extern "C" void kernel_launch(void* const* d_in, const int* in_sizes, int n_in,
                              void* d_out, int out_size) {
    const float* x     = (const float*)d_in[0];
    const float* qkvw  = (const float*)d_in[1];
    const float* ow    = (const float*)d_in[2];
    const float* gamma = (const float*)d_in[3];
    const float* beta  = (const float*)d_in[4];
    float* out = (float*)d_out;

    __nv_bfloat16 *xn, *wqkv, *wo, *qkv, *pr, *av;
    float *sc;
    cudaGetSymbolAddress((void**)&xn,   g_xn);
    cudaGetSymbolAddress((void**)&wqkv, g_wqkv);
    cudaGetSymbolAddress((void**)&wo,   g_wo);
    cudaGetSymbolAddress((void**)&qkv,  g_qkv);
    cudaGetSymbolAddress((void**)&sc,   g_sc);
    cudaGetSymbolAddress((void**)&pr,   g_pr);
    cudaGetSymbolAddress((void**)&av,   g_av);

    auto kQKV = gemm_bf16<false, 2, false, false, false>;
    auto kQKT = gemm_bf16<true,  0, true,  false, false>;
    auto kPV  = gemm_bf16<false, 2, false, true,  true>;
    auto kOP  = gemm_bf16<false, 1, false, false, true>;

    cudaFuncSetAttribute(kQKV, cudaFuncAttributeMaxDynamicSharedMemorySize, SMEM_BYTES);
    cudaFuncSetAttribute(kQKT, cudaFuncAttributeMaxDynamicSharedMemorySize, SMEM_BYTES);
    cudaFuncSetAttribute(kPV,  cudaFuncAttributeMaxDynamicSharedMemorySize, SMEM_BYTES);
    cudaFuncSetAttribute(kOP,  cudaFuncAttributeMaxDynamicSharedMemorySize, SMEM_BYTES);

    const int ROWS = BATCH * SEQ;  // 8192
    const long sQKV = (long)SEQ * NQKV;
    const long sSS  = (long)SEQ * SEQ;
    const long sSH  = (long)SEQ * HID;

    // PDL launch attribute (dependent may start during primary's epilogue)
    cudaLaunchAttribute pdl[1];
    pdl[0].id = cudaLaunchAttributeProgrammaticStreamSerialization;
    pdl[0].val.programmaticStreamSerializationAllowed = 1;

    // 1) fused prep: weight converts + LayerNorm (one launch, no PDL attr)
    const int n41 = HID * NQKV / 4, n42 = HID * HID / 4;
    const int nCvt = (n41 + n42 + 255) / 256;
    prep_kernel<<<nCvt + ROWS, 256>>>(
        (const float4*)qkvw, (uint32_t*)wqkv, n41,
        (const float4*)ow,   (uint32_t*)wo,   n42,
        nCvt, x, gamma, beta, xn);

    // 2) QKV projection: [8192,2048] @ [2048,6144] -> bf16
    {
        cudaLaunchConfig_t cfg = {};
        cfg.gridDim = dim3(NQKV / 128, ROWS / 128, 1);
        cfg.blockDim = dim3(GTHREADS, 1, 1);
        cfg.dynamicSmemBytes = SMEM_BYTES;
        cfg.attrs = pdl; cfg.numAttrs = 1;
        cudaLaunchKernelEx(&cfg, kQKV,
            (const __nv_bfloat16*)xn, (int)HID, 0L,
            (const __nv_bfloat16*)wqkv, (int)NQKV, 0L,
            (void*)qkv, (int)NQKV, 0L, (int)HID,
            (const float*)nullptr, 0);
    }

    // 3) scores = Q @ K^T per batch, packed lower-triangular grid -> fp32
    {
        const int nTri = (SEQ / 128) * (SEQ / 128 + 1) / 2;   // 136
        cudaLaunchConfig_t cfg = {};
        cfg.gridDim = dim3(nTri, 1, BATCH);
        cfg.blockDim = dim3(GTHREADS, 1, 1);
        cfg.dynamicSmemBytes = SMEM_BYTES;
        cfg.attrs = pdl; cfg.numAttrs = 1;
        cudaLaunchKernelEx(&cfg, kQKT,
            (const __nv_bfloat16*)qkv, (int)NQKV, sQKV,
            (const __nv_bfloat16*)(qkv + HID), (int)NQKV, sQKV,
            (void*)sc, (int)SEQ, sSS, (int)HID,
            (const float*)nullptr, 0);
    }

    // 4) causal softmax, single-pass in registers -> bf16 probs
    {
        cudaLaunchConfig_t cfg = {};
        cfg.gridDim = dim3(ROWS, 1, 1);
        cfg.blockDim = dim3(256, 1, 1);
        cfg.attrs = pdl; cfg.numAttrs = 1;
        cudaLaunchKernelEx(&cfg, softmax_kernel,
            (const float*)sc, (__nv_bfloat16*)pr, 1.0f / sqrtf((float)HID));
    }

    // 5) attn @ V per batch (K clipped at diagonal; heavy first; V prefilled)
    {
        cudaLaunchConfig_t cfg = {};
        cfg.gridDim = dim3(HID / 128, SEQ / 128, BATCH);
        cfg.blockDim = dim3(GTHREADS, 1, 1);
        cfg.dynamicSmemBytes = SMEM_BYTES;
        cfg.attrs = pdl; cfg.numAttrs = 1;
        cudaLaunchKernelEx(&cfg, kPV,
            (const __nv_bfloat16*)pr, (int)SEQ, sSS,
            (const __nv_bfloat16*)(qkv + 2 * HID), (int)NQKV, sQKV,
            (void*)av, (int)HID, sSH, (int)SEQ,
            (const float*)nullptr, 0);
    }

    // 6) O projection + residual (weights prefilled): -> fp32 out
    {
        cudaLaunchConfig_t cfg = {};
        cfg.gridDim = dim3(HID / 128, ROWS / 128, 1);
        cfg.blockDim = dim3(GTHREADS, 1, 1);
        cfg.dynamicSmemBytes = SMEM_BYTES;
        cfg.attrs = pdl; cfg.numAttrs = 1;
        cudaLaunchKernelEx(&cfg, kOP,
            (const __nv_bfloat16*)av, (int)HID, 0L,
            (const __nv_bfloat16*)wo, (int)HID, 0L,
            (void*)out, (int)HID, 0L, (int)HID,
            (const float*)x, (int)HID);
    }
}

// round 13
// speedup vs baseline: 1.0589x; 1.0081x over previous
#include <cuda_runtime.h>
#include <cuda_bf16.h>
#include <cstdint>
#include <math.h>

#define HID  2048
#define SEQ  2048
#define BATCH 4
#define NQKV 6144   // 3*HID

#define STAGES 3
#define BK 64
#define SSTRIDE 9216          // bf16 elems per operand per stage (128*72)
#define SMEM_BYTES (2 * STAGES * SSTRIDE * 2)   // 110592
#define GTHREADS 128          // 4 warps per CTA, warp tile 64x64

// ---------------- scratch (device globals; no allocations allowed) ----------
__device__ __align__(16) __nv_bfloat16 g_xn  [BATCH * SEQ * HID];    // 32 MB
__device__ __align__(16) __nv_bfloat16 g_wqkv[HID * NQKV];           // 24 MB
__device__ __align__(16) __nv_bfloat16 g_wo  [HID * HID];            //  8 MB
__device__ __align__(16) __nv_bfloat16 g_qkv [BATCH * SEQ * NQKV];   // 96 MB
__device__ __align__(16) __nv_bfloat16 g_sc  [BATCH * SEQ * SEQ];    // 32 MB bf16 scores
__device__ __align__(16) __nv_bfloat16 g_pr  [BATCH * SEQ * SEQ];    // 32 MB probs
__device__ __align__(16) __nv_bfloat16 g_av  [BATCH * SEQ * HID];    // 32 MB

// ---------------- helpers ----------------------------------------------------
__device__ __forceinline__ void cpa16(uint32_t dst, const void* src) {
    asm volatile("cp.async.cg.shared.global [%0], [%1], 16;" :: "r"(dst), "l"(src));
}
__device__ __forceinline__ void cpa_commit() {
    asm volatile("cp.async.commit_group;");
}
template <int N>
__device__ __forceinline__ void cpa_wait() {
    asm volatile("cp.async.wait_group %0;" :: "n"(N));
}
__device__ __forceinline__ void gdc_wait() {
    asm volatile("griddepcontrol.wait;" ::: "memory");
}
__device__ __forceinline__ void gdc_launch() {
    asm volatile("griddepcontrol.launch_dependents;" ::: "memory");
}

// ---------------- fused prep: weight converts + LayerNorm --------------------
__global__ void prep_kernel(const float4* __restrict__ w1, uint32_t* __restrict__ o1, int n41,
                            const float4* __restrict__ w2, uint32_t* __restrict__ o2, int n42,
                            int nCvt,
                            const float* __restrict__ x,
                            const float* __restrict__ gamma,
                            const float* __restrict__ beta,
                            __nv_bfloat16* __restrict__ xn) {
    if (blockIdx.x < (unsigned)nCvt) {
        int i = blockIdx.x * blockDim.x + threadIdx.x;
        const float4* in; uint32_t* out;
        if (i < n41) { in = w1; out = o1; }
        else if (i < n41 + n42) { in = w2 - n41; out = o2 - (size_t)n41 * 2; }
        else return;
        float4 v = in[i];
        __nv_bfloat162 a = __float22bfloat162_rn(make_float2(v.x, v.y));
        __nv_bfloat162 b = __float22bfloat162_rn(make_float2(v.z, v.w));
        out[(size_t)i * 2 + 0] = *reinterpret_cast<uint32_t*>(&a);
        out[(size_t)i * 2 + 1] = *reinterpret_cast<uint32_t*>(&b);
        return;
    }

    // LayerNorm: one block per row, fully vectorized (float4 in, 8B out)
    const int row = blockIdx.x - nCvt;
    const float4* xr4 = reinterpret_cast<const float4*>(x + (size_t)row * HID);
    const float4* g4  = reinterpret_cast<const float4*>(gamma);
    const float4* b4  = reinterpret_cast<const float4*>(beta);
    __nv_bfloat16* orow = xn + (size_t)row * HID;
    const int tid = threadIdx.x;

    float4 vv[2];
    float s = 0.f, s2 = 0.f;
#pragma unroll
    for (int i = 0; i < 2; i++) {
        float4 t = xr4[tid + i * 256];
        vv[i] = t;
        s  += t.x + t.y + t.z + t.w;
        s2 += t.x * t.x + t.y * t.y + t.z * t.z + t.w * t.w;
    }
    __shared__ float red[2][8];
#pragma unroll
    for (int o = 16; o > 0; o >>= 1) {
        s  += __shfl_down_sync(0xffffffffu, s,  o);
        s2 += __shfl_down_sync(0xffffffffu, s2, o);
    }
    const int w = tid >> 5, l = tid & 31;
    if (l == 0) { red[0][w] = s; red[1][w] = s2; }
    __syncthreads();
    if (w == 0) {
        float a  = red[0][l & 7];
        float b2 = red[1][l & 7];
#pragma unroll
        for (int o = 4; o > 0; o >>= 1) {
            a  += __shfl_down_sync(0xffffffffu, a,  o);
            b2 += __shfl_down_sync(0xffffffffu, b2, o);
        }
        if (l == 0) { red[0][0] = a; red[1][0] = b2; }
    }
    __syncthreads();
    const float mean = red[0][0] * (1.f / HID);
    const float var  = red[1][0] * (1.f / HID) - mean * mean;
    const float rstd = rsqrtf(var + 1e-5f);
#pragma unroll
    for (int i = 0; i < 2; i++) {
        float4 gm = g4[tid + i * 256];
        float4 bt = b4[tid + i * 256];
        float4 t = vv[i];
        __nv_bfloat162 h0 = __float22bfloat162_rn(make_float2(
            (t.x - mean) * rstd * gm.x + bt.x, (t.y - mean) * rstd * gm.y + bt.y));
        __nv_bfloat162 h1 = __float22bfloat162_rn(make_float2(
            (t.z - mean) * rstd * gm.z + bt.z, (t.w - mean) * rstd * gm.w + bt.w));
        uint2 pk = make_uint2(*reinterpret_cast<uint32_t*>(&h0),
                              *reinterpret_cast<uint32_t*>(&h1));
        *reinterpret_cast<uint2*>(orow + (tid + i * 256) * 4) = pk;
    }
}

// ---------------- causal softmax: bf16 scores in, bf16 probs out -------------
// Fully vectorized: one uint4 (8 bf16) load + one uint4 store per thread.
__global__ void softmax_kernel(const __nv_bfloat16* __restrict__ sc,
                               __nv_bfloat16* __restrict__ pr, float scale) {
    const int row = blockIdx.x;            // b*SEQ + q
    const int q = row & (SEQ - 1);
    const __nv_bfloat16* p = sc + (size_t)row * SEQ;
    __nv_bfloat16* po = pr + (size_t)row * SEQ;
    const int n = q + 1;
    const int nend = ((q >> 7) + 1) << 7;  // PV reads only [0, nend)
    const int tid = threadIdx.x;
    const int base = tid * 8;
    __shared__ float red[8];

    gdc_wait();   // scores from QKT must be visible

    float v[8];
    float mx = -1e30f;
    const bool active = base < n;
    if (active) {
        uint4 raw = *reinterpret_cast<const uint4*>(p + base);
        const __nv_bfloat162* h = reinterpret_cast<const __nv_bfloat162*>(&raw);
#pragma unroll
        for (int j = 0; j < 4; j++) {
            float2 f = __bfloat1622float2(h[j]);
            v[2 * j]     = f.x * scale;
            v[2 * j + 1] = f.y * scale;
        }
#pragma unroll
        for (int j = 0; j < 8; j++)
            if (base + j < n) mx = fmaxf(mx, v[j]);
    }
#pragma unroll
    for (int o = 16; o > 0; o >>= 1) mx = fmaxf(mx, __shfl_down_sync(0xffffffffu, mx, o));
    if ((tid & 31) == 0) red[tid >> 5] = mx;
    __syncthreads();
    if (tid < 32) {
        float a = red[tid & 7];
#pragma unroll
        for (int o = 4; o > 0; o >>= 1) a = fmaxf(a, __shfl_down_sync(0xffffffffu, a, o));
        if (tid == 0) red[0] = a;
    }
    __syncthreads();
    mx = red[0];
    __syncthreads();

    float sum = 0.f;
    if (active) {
#pragma unroll
        for (int j = 0; j < 8; j++) {
            if (base + j < n) { v[j] = __expf(v[j] - mx); sum += v[j]; }
            else v[j] = 0.f;
        }
    }
#pragma unroll
    for (int o = 16; o > 0; o >>= 1) sum += __shfl_down_sync(0xffffffffu, sum, o);
    if ((tid & 31) == 0) red[tid >> 5] = sum;
    __syncthreads();
    if (tid < 32) {
        float a = red[tid & 7];
#pragma unroll
        for (int o = 4; o > 0; o >>= 1) a += __shfl_down_sync(0xffffffffu, a, o);
        if (tid == 0) red[0] = a;
    }
    __syncthreads();
    gdc_launch();
    const float inv = 1.f / red[0];
    if (base < nend) {
        uint4 outv;
        __nv_bfloat162* ho = reinterpret_cast<__nv_bfloat162*>(&outv);
#pragma unroll
        for (int j = 0; j < 4; j++) {
            float a = active ? v[2 * j] * inv : 0.f;
            float b = active ? v[2 * j + 1] * inv : 0.f;
            ho[j] = __float22bfloat162_rn(make_float2(a, b));
        }
        *reinterpret_cast<uint4*>(po + base) = outv;
    }
}

// ---------------- bf16 tensor-core GEMM (3-stage, BK=64, 4 warps 64x64) ------
// C[M,N] = A[M,K] @ B. A row-major bf16 (lda).
// BKMAJ=true:  B stored [N,K] k-contig (ldb) -> A @ B^T.
// BKMAJ=false: B stored [K,N] n-contig (ldb).
// EPI: 0 = fp32 out, 1 = fp32 out + residual R, 2 = bf16 out.
// TRIPACK: grid.x is a packed lower-triangular (mb,nb) index.
// CKLIM: clip K at diagonal; mb order reversed (heavy blocks first).
// PREB: B operand is NOT produced by the primary kernel -> prefill before wait.
// Block 128x128x64, 4 warps of 64x64 (1 warp/SMSP/CTA), 2 CTAs/SM.
template <bool BKMAJ, int EPI, bool TRIPACK, bool CKLIM, bool PREB>
__global__ void __launch_bounds__(GTHREADS, 2)
gemm_bf16(const __nv_bfloat16* __restrict__ A, int lda, long sA,
          const __nv_bfloat16* __restrict__ B, int ldb, long sB,
          void* __restrict__ Cv, int ldc, long sC,
          int Kdim,
          const float* __restrict__ R, int ldr) {
    int mb, nb;
    if (TRIPACK) {
        const int t = blockIdx.x;
        int m = (int)((sqrtf(8.f * t + 1.f) - 1.f) * 0.5f);
        while ((m + 1) * (m + 2) / 2 <= t) m++;
        while (m * (m + 1) / 2 > t) m--;
        mb = m;
        nb = t - m * (m + 1) / 2;
    } else {
        mb = CKLIM ? (gridDim.y - 1 - blockIdx.y) : blockIdx.y;
        nb = blockIdx.x;
    }

    A += (long)blockIdx.z * sA;
    B += (long)blockIdx.z * sB;

    const int kend = CKLIM ? min(Kdim, (mb + 1) * 128) : Kdim;
    const int nK = kend >> 6;   // BK = 64

    extern __shared__ __align__(16) __nv_bfloat16 sm[];
    const uint32_t smBase = (uint32_t)__cvta_generic_to_shared(sm);
    const uint32_t aBase = smBase;
    const uint32_t bBase = smBase + STAGES * SSTRIDE * 2;

    const int tid = threadIdx.x;
    const int warp = tid >> 5, lane = tid & 31;
    const int gid = lane >> 2, tig = lane & 3;
    const int wm = (warp & 1) * 64, wn = (warp >> 1) * 64;
    const int bm0 = mb * 128, bn0 = nb * 128;

    float c[4][8][4];
#pragma unroll
    for (int i = 0; i < 4; i++)
#pragma unroll
        for (int j = 0; j < 8; j++)
#pragma unroll
            for (int k = 0; k < 4; k++) c[i][j][k] = 0.f;

    // ldmatrix per-lane coordinates
    const int arow = (lane & 7) + ((lane >> 3) & 1) * 8;
    const int acol = ((lane >> 4) & 1) * 8;
    const int ln8 = lane & 7, sel = lane >> 3;
    const int bt_row = ((sel >> 1) & 1) * 8 + ln8;   // BKMAJ=true: n within 16
    const int bt_col = (sel & 1) * 8;                // k-half
    const int bf_row = (sel & 1) * 8 + ln8;          // BKMAJ=false: k within 16
    const int bf_col = ((sel >> 1) & 1) * 8;         // n within 16

    auto fillA = [&](int st, int k0) {
#pragma unroll
        for (int p = 0; p < 8; p++) {
            int fid = tid + p * GTHREADS;
            int r = fid >> 3, kq = fid & 7;
            cpa16(aBase + (st * SSTRIDE + r * 72 + kq * 8) * 2,
                  A + (size_t)(bm0 + r) * lda + k0 + kq * 8);
        }
    };
    auto fillB = [&](int st, int k0) {
#pragma unroll
        for (int p = 0; p < 8; p++) {
            int fid = tid + p * GTHREADS;
            if (BKMAJ) {
                int r = fid >> 3, kq = fid & 7;
                cpa16(bBase + (st * SSTRIDE + r * 72 + kq * 8) * 2,
                      B + (size_t)(bn0 + r) * ldb + k0 + kq * 8);
            } else {
                int kr = fid >> 4, nq = fid & 15;
                cpa16(bBase + (st * SSTRIDE + kr * 136 + nq * 8) * 2,
                      B + (size_t)(k0 + kr) * ldb + bn0 + nq * 8);
            }
        }
    };

    // prologue with PDL: B that doesn't come from the primary fills pre-wait.
    if (PREB) { fillB(0, 0); fillB(1, BK); }
    gdc_wait();
    fillA(0, 0); if (!PREB) fillB(0, 0);
    cpa_commit();
    fillA(1, BK); if (!PREB) fillB(1, BK);
    cpa_commit();

    int buf = 0, fb = STAGES - 1;
    for (int kt = 0; kt < nK; kt++) {
        cpa_wait<STAGES - 2>();
        __syncthreads();

        const int kf = kt + STAGES - 1;
        if (kf < nK) { fillA(fb, kf * BK); fillB(fb, kf * BK); }
        cpa_commit();

        const uint32_t aS = aBase + buf * SSTRIDE * 2;
        const uint32_t bS = bBase + buf * SSTRIDE * 2;

#pragma unroll
        for (int kc = 0; kc < 4; kc++) {
            const int kk = kc * 16;
            uint32_t af[4][4], bfr[4][4];
#pragma unroll
            for (int mf = 0; mf < 4; mf++) {
                uint32_t a = aS + ((wm + mf * 16 + arow) * 72 + acol + kk) * 2;
                asm volatile("ldmatrix.sync.aligned.m8n8.x4.shared.b16 {%0,%1,%2,%3},[%4];"
                    : "=r"(af[mf][0]), "=r"(af[mf][1]), "=r"(af[mf][2]), "=r"(af[mf][3])
                    : "r"(a));
            }
#pragma unroll
            for (int nfp = 0; nfp < 4; nfp++) {
                if (BKMAJ) {
                    uint32_t a = bS + ((wn + nfp * 16 + bt_row) * 72 + kk + bt_col) * 2;
                    asm volatile("ldmatrix.sync.aligned.m8n8.x4.shared.b16 {%0,%1,%2,%3},[%4];"
                        : "=r"(bfr[nfp][0]), "=r"(bfr[nfp][1]),
                          "=r"(bfr[nfp][2]), "=r"(bfr[nfp][3])
                        : "r"(a));
                } else {
                    uint32_t a = bS + ((kk + bf_row) * 136 + wn + nfp * 16 + bf_col) * 2;
                    asm volatile("ldmatrix.sync.aligned.m8n8.x4.trans.shared.b16 {%0,%1,%2,%3},[%4];"
                        : "=r"(bfr[nfp][0]), "=r"(bfr[nfp][1]),
                          "=r"(bfr[nfp][2]), "=r"(bfr[nfp][3])
                        : "r"(a));
                }
            }
#pragma unroll
            for (int mf = 0; mf < 4; mf++)
#pragma unroll
                for (int nf = 0; nf < 8; nf++) {
                    asm volatile(
                        "mma.sync.aligned.m16n8k16.row.col.f32.bf16.bf16.f32 "
                        "{%0,%1,%2,%3},{%4,%5,%6,%7},{%8,%9},{%0,%1,%2,%3};"
                        : "+f"(c[mf][nf][0]), "+f"(c[mf][nf][1]),
                          "+f"(c[mf][nf][2]), "+f"(c[mf][nf][3])
                        : "r"(af[mf][0]), "r"(af[mf][1]), "r"(af[mf][2]), "r"(af[mf][3]),
                          "r"(bfr[nf >> 1][(nf & 1) * 2]), "r"(bfr[nf >> 1][(nf & 1) * 2 + 1]));
                }
        }

        buf = (buf + 1 == STAGES) ? 0 : buf + 1;
        fb  = (fb  + 1 == STAGES) ? 0 : fb  + 1;
    }

    gdc_launch();

    // epilogue
    if (EPI == 2) {
        __nv_bfloat16* C = (__nv_bfloat16*)Cv + (long)blockIdx.z * sC;
#pragma unroll
        for (int mf = 0; mf < 4; mf++) {
            const int r0 = bm0 + wm + mf * 16 + gid;
#pragma unroll
            for (int nf = 0; nf < 8; nf++) {
                const int cc = bn0 + wn + nf * 8 + tig * 2;
                __nv_bfloat162 v0 = __float22bfloat162_rn(make_float2(c[mf][nf][0], c[mf][nf][1]));
                __nv_bfloat162 v1 = __float22bfloat162_rn(make_float2(c[mf][nf][2], c[mf][nf][3]));
                *reinterpret_cast<__nv_bfloat162*>(C + (size_t)r0 * ldc + cc) = v0;
                *reinterpret_cast<__nv_bfloat162*>(C + (size_t)(r0 + 8) * ldc + cc) = v1;
            }
        }
    } else {
        float* C = (float*)Cv + (long)blockIdx.z * sC;
#pragma unroll
        for (int mf = 0; mf < 4; mf++) {
            const int r0 = bm0 + wm + mf * 16 + gid;
#pragma unroll
            for (int nf = 0; nf < 8; nf++) {
                const int cc = bn0 + wn + nf * 8 + tig * 2;
                float2 v0 = make_float2(c[mf][nf][0], c[mf][nf][1]);
                float2 v1 = make_float2(c[mf][nf][2], c[mf][nf][3]);
                if (EPI == 1) {
                    const float2 q0 = *reinterpret_cast<const float2*>(R + (size_t)r0 * ldr + cc);
                    const float2 q1 = *reinterpret_cast<const float2*>(R + (size_t)(r0 + 8) * ldr + cc);
                    v0.x += q0.x; v0.y += q0.y;
                    v1.x += q1.x; v1.y += q1.y;
                }
                *reinterpret_cast<float2*>(C + (size_t)r0 * ldc + cc) = v0;
                *reinterpret_cast<float2*>(C + (size_t)(r0 + 8) * ldc + cc) = v1;
            }
        }
    }
}

// ---------------- launch ------------------------------------------------------
extern "C" void kernel_launch(void* const* d_in, const int* in_sizes, int n_in,
                              void* d_out, int out_size) {
    const float* x     = (const float*)d_in[0];
    const float* qkvw  = (const float*)d_in[1];
    const float* ow    = (const float*)d_in[2];
    const float* gamma = (const float*)d_in[3];
    const float* beta  = (const float*)d_in[4];
    float* out = (float*)d_out;

    __nv_bfloat16 *xn, *wqkv, *wo, *qkv, *sc, *pr, *av;
    cudaGetSymbolAddress((void**)&xn,   g_xn);
    cudaGetSymbolAddress((void**)&wqkv, g_wqkv);
    cudaGetSymbolAddress((void**)&wo,   g_wo);
    cudaGetSymbolAddress((void**)&qkv,  g_qkv);
    cudaGetSymbolAddress((void**)&sc,   g_sc);
    cudaGetSymbolAddress((void**)&pr,   g_pr);
    cudaGetSymbolAddress((void**)&av,   g_av);

    auto kQKV = gemm_bf16<false, 2, false, false, false>;
    auto kQKT = gemm_bf16<true,  2, true,  false, false>;
    auto kPV  = gemm_bf16<false, 2, false, true,  true>;
    auto kOP  = gemm_bf16<false, 1, false, false, true>;

    cudaFuncSetAttribute(kQKV, cudaFuncAttributeMaxDynamicSharedMemorySize, SMEM_BYTES);
    cudaFuncSetAttribute(kQKT, cudaFuncAttributeMaxDynamicSharedMemorySize, SMEM_BYTES);
    cudaFuncSetAttribute(kPV,  cudaFuncAttributeMaxDynamicSharedMemorySize, SMEM_BYTES);
    cudaFuncSetAttribute(kOP,  cudaFuncAttributeMaxDynamicSharedMemorySize, SMEM_BYTES);

    const int ROWS = BATCH * SEQ;  // 8192
    const long sQKV = (long)SEQ * NQKV;
    const long sSS  = (long)SEQ * SEQ;
    const long sSH  = (long)SEQ * HID;

    cudaLaunchAttribute pdl[1];
    pdl[0].id = cudaLaunchAttributeProgrammaticStreamSerialization;
    pdl[0].val.programmaticStreamSerializationAllowed = 1;

    // 1) fused prep: weight converts + LayerNorm (one launch)
    const int n41 = HID * NQKV / 4, n42 = HID * HID / 4;
    const int nCvt = (n41 + n42 + 255) / 256;
    prep_kernel<<<nCvt + ROWS, 256>>>(
        (const float4*)qkvw, (uint32_t*)wqkv, n41,
        (const float4*)ow,   (uint32_t*)wo,   n42,
        nCvt, x, gamma, beta, xn);

    // 2) QKV projection: [8192,2048] @ [2048,6144] -> bf16
    {
        cudaLaunchConfig_t cfg = {};
        cfg.gridDim = dim3(NQKV / 128, ROWS / 128, 1);
        cfg.blockDim = dim3(GTHREADS, 1, 1);
        cfg.dynamicSmemBytes = SMEM_BYTES;
        cfg.attrs = pdl; cfg.numAttrs = 1;
        cudaLaunchKernelEx(&cfg, kQKV,
            (const __nv_bfloat16*)xn, (int)HID, 0L,
            (const __nv_bfloat16*)wqkv, (int)NQKV, 0L,
            (void*)qkv, (int)NQKV, 0L, (int)HID,
            (const float*)nullptr, 0);
    }

    // 3) scores = Q @ K^T per batch, packed lower-triangular grid -> bf16
    {
        const int nTri = (SEQ / 128) * (SEQ / 128 + 1) / 2;   // 136
        cudaLaunchConfig_t cfg = {};
        cfg.gridDim = dim3(nTri, 1, BATCH);
        cfg.blockDim = dim3(GTHREADS, 1, 1);
        cfg.dynamicSmemBytes = SMEM_BYTES;
        cfg.attrs = pdl; cfg.numAttrs = 1;
        cudaLaunchKernelEx(&cfg, kQKT,
            (const __nv_bfloat16*)qkv, (int)NQKV, sQKV,
            (const __nv_bfloat16*)(qkv + HID), (int)NQKV, sQKV,
            (void*)sc, (int)SEQ, sSS, (int)HID,
            (const float*)nullptr, 0);
    }

    // 4) causal softmax, vectorized bf16 in/out
    {
        cudaLaunchConfig_t cfg = {};
        cfg.gridDim = dim3(ROWS, 1, 1);
        cfg.blockDim = dim3(256, 1, 1);
        cfg.attrs = pdl; cfg.numAttrs = 1;
        cudaLaunchKernelEx(&cfg, softmax_kernel,
            (const __nv_bfloat16*)sc, (__nv_bfloat16*)pr, 1.0f / sqrtf((float)HID));
    }

    // 5) attn @ V per batch (K clipped at diagonal; heavy first; V prefilled)
    {
        cudaLaunchConfig_t cfg = {};
        cfg.gridDim = dim3(HID / 128, SEQ / 128, BATCH);
        cfg.blockDim = dim3(GTHREADS, 1, 1);
        cfg.dynamicSmemBytes = SMEM_BYTES;
        cfg.attrs = pdl; cfg.numAttrs = 1;
        cudaLaunchKernelEx(&cfg, kPV,
            (const __nv_bfloat16*)pr, (int)SEQ, sSS,
            (const __nv_bfloat16*)(qkv + 2 * HID), (int)NQKV, sQKV,
            (void*)av, (int)HID, sSH, (int)SEQ,
            (const float*)nullptr, 0);
    }

    // 6) O projection + residual (weights prefilled): -> fp32 out
    {
        cudaLaunchConfig_t cfg = {};
        cfg.gridDim = dim3(HID / 128, ROWS / 128, 1);
        cfg.blockDim = dim3(GTHREADS, 1, 1);
        cfg.dynamicSmemBytes = SMEM_BYTES;
        cfg.attrs = pdl; cfg.numAttrs = 1;
        cudaLaunchKernelEx(&cfg, kOP,
            (const __nv_bfloat16*)av, (int)HID, 0L,
            (const __nv_bfloat16*)wo, (int)HID, 0L,
            (void*)out, (int)HID, 0L, (int)HID,
            (const float*)x, (int)HID);
    }
}